// round 11
// baseline (speedup 1.0000x reference)
#include <cuda_runtime.h>
#include <cuda_fp16.h>
#include <cstdint>
#include <math.h>

#define NE 8
#define DIM 1024
#define IDIM 2048
#define TKN_MAX 8192
#define ASG_MAX 16384

typedef __half fp16;

// ---------------- device scratch (no allocs allowed) ----------------
__device__ float g_G[(size_t)ASG_MAX * IDIM];
__device__ float g_pair[(size_t)ASG_MAX * DIM];
__device__ fp16  g_Hhi[(size_t)ASG_MAX * IDIM];
__device__ fp16  g_Hlo[(size_t)ASG_MAX * IDIM];
__device__ fp16  g_xhi[(size_t)TKN_MAX * DIM];
__device__ fp16  g_xlo[(size_t)TKN_MAX * DIM];
__device__ fp16  g_xghi[(size_t)ASG_MAX * DIM];
__device__ fp16  g_xglo[(size_t)ASG_MAX * DIM];
// transposed weights [N, K], single fp16
__device__ fp16  g_sgT[(size_t)IDIM * DIM];
__device__ fp16  g_suT[(size_t)IDIM * DIM];
__device__ fp16  g_sdT[(size_t)DIM * IDIM];
__device__ fp16  g_egT[(size_t)NE * IDIM * DIM];
__device__ fp16  g_euT[(size_t)NE * IDIM * DIM];
__device__ fp16  g_edT[(size_t)NE * DIM * IDIM];
__device__ int   g_assign[ASG_MAX];
__device__ int   g_te[ASG_MAX];
__device__ float g_tw[ASG_MAX];
__device__ int   g_slot[ASG_MAX];
__device__ int   g_counts[NE];
__device__ int   g_off[NE + 1];
__device__ int   g_cursor[NE];
__device__ float g_psum[NE];

// ---------------- mma / ldmatrix / cp.async helpers ----------------
__device__ __forceinline__ void mma_f16(float* d, const unsigned* a, const unsigned* b) {
    asm volatile("mma.sync.aligned.m16n8k16.row.col.f32.f16.f16.f32 "
                 "{%0,%1,%2,%3}, {%4,%5,%6,%7}, {%8,%9}, {%0,%1,%2,%3};"
                 : "+f"(d[0]), "+f"(d[1]), "+f"(d[2]), "+f"(d[3])
                 : "r"(a[0]), "r"(a[1]), "r"(a[2]), "r"(a[3]), "r"(b[0]), "r"(b[1]));
}
__device__ __forceinline__ void ldsm4(unsigned* r, unsigned addr) {
    asm volatile("ldmatrix.sync.aligned.m8n8.x4.shared.b16 {%0,%1,%2,%3}, [%4];"
                 : "=r"(r[0]), "=r"(r[1]), "=r"(r[2]), "=r"(r[3]) : "r"(addr));
}
#define CPA16(dst, src) \
    asm volatile("cp.async.cg.shared.global [%0], [%1], 16;" :: "r"(dst), "l"(src))
#define CP_COMMIT() asm volatile("cp.async.commit_group;" ::: "memory")
#define CP_WAIT1()  asm volatile("cp.async.wait_group 1;" ::: "memory")

__device__ __forceinline__ float silu_f(float x) { return x / (1.f + expf(-x)); }

// ---------------- init ----------------
__global__ void k_init() {
    int i = threadIdx.x;
    if (i < NE) { g_counts[i] = 0; g_psum[i] = 0.f; }
}

// ---------------- split: fp32 -> fp16 hi + fp16 lo ----------------
__global__ void k_split(const float4* __restrict__ in, __half2* __restrict__ hi,
                        __half2* __restrict__ lo, int n4) {
    int i = blockIdx.x * blockDim.x + threadIdx.x;
    if (i < n4) {
        float4 v = in[i];
        fp16 h0 = __float2half_rn(v.x), h1 = __float2half_rn(v.y);
        fp16 h2 = __float2half_rn(v.z), h3 = __float2half_rn(v.w);
        fp16 l0 = __float2half_rn(v.x - __half2float(h0));
        fp16 l1 = __float2half_rn(v.y - __half2float(h1));
        fp16 l2 = __float2half_rn(v.z - __half2float(h2));
        fp16 l3 = __float2half_rn(v.w - __half2float(h3));
        hi[2 * i]     = __halves2half2(h0, h1);
        hi[2 * i + 1] = __halves2half2(h2, h3);
        lo[2 * i]     = __halves2half2(l0, l1);
        lo[2 * i + 1] = __halves2half2(l2, l3);
    }
}

// ---------------- transpose + convert: W[K,N] fp32 -> Wt[N,K] fp16 ----------------
__global__ void k_tsplit(const float* __restrict__ W, fp16* __restrict__ hi, int K, int N) {
    __shared__ float t[32][33];
    size_t eo = (size_t)blockIdx.z * K * N;
    int k0 = blockIdx.y * 32, n0 = blockIdx.x * 32;
    int tx = threadIdx.x & 31, ty = threadIdx.x >> 5;
#pragma unroll
    for (int r = ty; r < 32; r += 8)
        t[r][tx] = W[eo + (size_t)(k0 + r) * N + n0 + tx];
    __syncthreads();
#pragma unroll
    for (int r = ty; r < 32; r += 8) {
        size_t o = eo + (size_t)(n0 + r) * K + k0 + tx;
        hi[o] = __float2half_rn(t[tx][r]);
    }
}

// ---------------- gather + split ----------------
__global__ void k_gsplit(const float* __restrict__ x, __half2* __restrict__ hi,
                         __half2* __restrict__ lo) {
    int a = blockIdx.x;
    int t = g_assign[a];
    const float4* src = (const float4*)(x + (size_t)t * DIM);
    int i = threadIdx.x;
    float4 v = src[i];
    fp16 h0 = __float2half_rn(v.x), h1 = __float2half_rn(v.y);
    fp16 h2 = __float2half_rn(v.z), h3 = __float2half_rn(v.w);
    fp16 l0 = __float2half_rn(v.x - __half2float(h0));
    fp16 l1 = __float2half_rn(v.y - __half2float(h1));
    fp16 l2 = __float2half_rn(v.z - __half2float(h2));
    fp16 l3 = __float2half_rn(v.w - __half2float(h3));
    size_t o = (size_t)a * (DIM / 2) + 2 * i;
    hi[o]     = __halves2half2(h0, h1);
    hi[o + 1] = __halves2half2(h2, h3);
    lo[o]     = __halves2half2(l0, l1);
    lo[o + 1] = __halves2half2(l2, l3);
}

// ---------------- router ----------------
__global__ void k_router(const float* __restrict__ x, const float* __restrict__ gw, int T) {
    __shared__ float sP[NE];
    if (threadIdx.x < NE) sP[threadIdx.x] = 0.f;
    __syncthreads();

    int warp = (blockIdx.x * blockDim.x + threadIdx.x) >> 5;
    int lane = threadIdx.x & 31;
    if (warp < T) {
        const float* xr = x + (size_t)warp * DIM;
        float acc[NE];
#pragma unroll
        for (int e = 0; e < NE; e++) acc[e] = 0.f;
        for (int i = lane; i < DIM; i += 32) {
            float xv = xr[i];
#pragma unroll
            for (int e = 0; e < NE; e++) acc[e] = fmaf(xv, gw[e * DIM + i], acc[e]);
        }
#pragma unroll
        for (int e = 0; e < NE; e++) {
#pragma unroll
            for (int o = 16; o; o >>= 1) acc[e] += __shfl_xor_sync(0xffffffffu, acc[e], o);
        }
        if (lane == 0) {
            float mx = acc[0];
#pragma unroll
            for (int e = 1; e < NE; e++) mx = fmaxf(mx, acc[e]);
            float ex[NE]; float s = 0.f;
#pragma unroll
            for (int e = 0; e < NE; e++) { ex[e] = expf(acc[e] - mx); s += ex[e]; }
            float inv = 1.f / s;
#pragma unroll
            for (int e = 0; e < NE; e++) atomicAdd(&sP[e], ex[e] * inv);
            int i0 = 0;
#pragma unroll
            for (int e = 1; e < NE; e++) if (acc[e] > acc[i0]) i0 = e;
            int i1 = (i0 == 0) ? 1 : 0;
#pragma unroll
            for (int e = 0; e < NE; e++) if (e != i0 && acc[e] > acc[i1]) i1 = e;
            float m2 = fmaxf(acc[i0], acc[i1]);
            float e0 = expf(acc[i0] - m2), e1 = expf(acc[i1] - m2);
            float wsum = e0 + e1;
            g_te[2 * warp] = i0; g_te[2 * warp + 1] = i1;
            g_tw[2 * warp] = e0 / wsum; g_tw[2 * warp + 1] = e1 / wsum;
            atomicAdd(&g_counts[i0], 1);
            atomicAdd(&g_counts[i1], 1);
        }
    }
    __syncthreads();
    if (threadIdx.x < NE) atomicAdd(&g_psum[threadIdx.x], sP[threadIdx.x]);
}

// ---------------- scan ----------------
__global__ void k_scan(float* __restrict__ out, int T, int write_aux) {
    if (threadIdx.x == 0 && blockIdx.x == 0) {
        int o = 0;
        float aux = 0.f;
        for (int e = 0; e < NE; e++) {
            g_off[e] = o; g_cursor[e] = o;
            float f = (float)g_counts[e] / (float)(T * 2);
            float P = g_psum[e] / (float)T;
            aux += f * P;
            o += g_counts[e];
        }
        g_off[NE] = o;
        if (write_aux) out[(size_t)T * DIM] = (float)NE * aux;
    }
}

// ---------------- scatter ----------------
__global__ void k_scatter(int T) {
    int t = blockIdx.x * blockDim.x + threadIdx.x;
    if (t < T) {
#pragma unroll
        for (int k = 0; k < 2; k++) {
            int e = g_te[2 * t + k];
            int pos = atomicAdd(&g_cursor[e], 1);
            g_assign[pos] = t;
            g_slot[2 * t + k] = pos;
        }
    }
}

// ---------------- fp16 A-split x2 HMMA GEMM: CTA 128x256, warp 64x64 ----------------
// C[m,n] = sum_k (Ahi+Alo)[m,k] * Bt[n,k];  B single fp16, fp32 accumulate.
// BK=64 (row = 128B line), SW128 swizzle, 3-stage cp.async ring (64KB/stage).
#define BK 64
#define STG 3
#define TILE_A_B 16384                  // 128 rows x 128B
#define TILE_B_B 32768                  // 256 rows x 128B
#define OFF_ALO  TILE_A_B
#define OFF_B    (2 * TILE_A_B)
#define STAGE_B  (2 * TILE_A_B + TILE_B_B)      // 65536
#define GEMM_SMEM (STG * STAGE_B)               // 196608

template <int EPI>
__global__ __launch_bounds__(256) void k_gemm_p(
    const fp16* __restrict__ Ahi, const fp16* __restrict__ Alo,
    const fp16* __restrict__ Bt,
    float* __restrict__ C, const float* __restrict__ Gbuf,
    fp16* __restrict__ Hhi, fp16* __restrict__ Hlo,
    const int* __restrict__ seg_off,
    int M, int N, int K, long strideB, int NST)
{
    int m_lo = 0, m_hi = M;
    const fp16* Bp = Bt;
    if (seg_off) {
        int s = blockIdx.z;
        m_lo = seg_off[s]; m_hi = seg_off[s + 1];
        Bp += (size_t)s * strideB;
    }
    int m0 = m_lo + blockIdx.y * 128;
    if (m0 >= m_hi) return;
    int n0 = blockIdx.x * 256;

    extern __shared__ __align__(1024) char sm[];
    int tid = threadIdx.x, lane = tid & 31, wid = tid >> 5;
    int wm = wid >> 2, wn = wid & 3;

    unsigned sbase;
    asm("{ .reg .u64 t; cvta.to.shared.u64 t, %1; cvt.u32.u64 %0, t; }"
        : "=r"(sbase) : "l"(sm));

    // ---- load addressing ----
    int chunk = tid & 7;
    int r0 = tid >> 3;                  // 0..31
    unsigned rowA[4];
#pragma unroll
    for (int j = 0; j < 4; j++) {
        int r = r0 + 32 * j;
        int gr = m0 + r; if (gr > M - 1) gr = M - 1;
        rowA[j] = (unsigned)((size_t)gr * K * 2) + (unsigned)(chunk * 16);
    }
    unsigned rowB0 = (unsigned)((size_t)(n0 + r0) * K * 2) + (unsigned)(chunk * 16);
    unsigned rowBstep = (unsigned)(32 * K * 2);
    unsigned dst0 = (unsigned)(r0 * 128 + ((chunk * 16) ^ ((r0 & 7) << 4)));

    auto load_stage = [&](int stage, int buf) {
        unsigned d = sbase + (unsigned)buf * STAGE_B + dst0;
        unsigned ko = (unsigned)(stage * BK * 2);
#pragma unroll
        for (int j = 0; j < 4; j++) {
            unsigned dj = d + (unsigned)j * 4096;
            CPA16(dj,           (const char*)Ahi + rowA[j] + ko);
            CPA16(dj + OFF_ALO, (const char*)Alo + rowA[j] + ko);
        }
#pragma unroll
        for (int j = 0; j < 8; j++) {
            unsigned dj = d + (unsigned)j * 4096;
            CPA16(dj + OFF_B, (const char*)Bp + rowB0 + (unsigned)j * rowBstep + ko);
        }
    };

    // ---- accumulators ----
    float acc[4][8][4];
#pragma unroll
    for (int i = 0; i < 4; i++)
#pragma unroll
        for (int j = 0; j < 8; j++)
#pragma unroll
            for (int r = 0; r < 4; r++) acc[i][j][r] = 0.f;

    unsigned laneRow = (unsigned)((lane & 15) * 128);
    unsigned chunkb = (unsigned)((lane >> 4) << 4);
    unsigned swx = (unsigned)((lane & 7) << 4);

    // ---- prologue ----
    if (0 < NST) load_stage(0, 0);
    CP_COMMIT();
    if (1 < NST) load_stage(1, 1);
    CP_COMMIT();

    for (int i = 0; i < NST; i++) {
        CP_WAIT1();
        __syncthreads();
        if (i + 2 < NST) load_stage(i + 2, (i + 2) % STG);
        CP_COMMIT();

        unsigned tb = sbase + (unsigned)(i % STG) * STAGE_B;

#pragma unroll
        for (int ks = 0; ks < 4; ks++) {
            unsigned xoff = (((unsigned)(ks * 32)) | chunkb) ^ swx;
            unsigned bfr[8][2];
#pragma unroll
            for (int nb = 0; nb < 4; nb++) {
                unsigned ro = (unsigned)((wn * 64 + nb * 16) * 128) + laneRow + xoff;
                unsigned t[4];
                ldsm4(t, tb + OFF_B + ro);
                bfr[2 * nb][0] = t[0]; bfr[2 * nb][1] = t[2];
                bfr[2 * nb + 1][0] = t[1]; bfr[2 * nb + 1][1] = t[3];
            }
            unsigned ah[4][4], al[4][4];
#pragma unroll
            for (int mi = 0; mi < 4; mi++) {
                unsigned ro = (unsigned)((wm * 64 + mi * 16) * 128) + laneRow + xoff;
                ldsm4(ah[mi], tb + ro);
                ldsm4(al[mi], tb + OFF_ALO + ro);
            }
#pragma unroll
            for (int mi = 0; mi < 4; mi++)
#pragma unroll
                for (int ni = 0; ni < 8; ni++) mma_f16(acc[mi][ni], ah[mi], bfr[ni]);
#pragma unroll
            for (int mi = 0; mi < 4; mi++)
#pragma unroll
                for (int ni = 0; ni < 8; ni++) mma_f16(acc[mi][ni], al[mi], bfr[ni]);
        }
        __syncthreads();
    }

    // ---- epilogue ----
    int mrow = m0 + wm * 64 + (lane >> 2);
    int mcol = n0 + wn * 64 + ((lane & 3) << 1);
#pragma unroll
    for (int mi = 0; mi < 4; mi++) {
#pragma unroll
        for (int half = 0; half < 2; half++) {
            int r = mrow + mi * 16 + half * 8;
            if (r >= m_hi) continue;
#pragma unroll
            for (int ni = 0; ni < 8; ni++) {
                int c = mcol + ni * 8;
                size_t idx = (size_t)r * N + c;
                float v0 = acc[mi][ni][2 * half];
                float v1 = acc[mi][ni][2 * half + 1];
                if (EPI == 0) {
                    *(float2*)(C + idx) = make_float2(v0, v1);
                } else {
                    float2 g = *(const float2*)(Gbuf + idx);
                    float h0 = silu_f(g.x) * v0;
                    float h1 = silu_f(g.y) * v1;
                    fp16 hh0 = __float2half_rn(h0);
                    fp16 hh1 = __float2half_rn(h1);
                    fp16 hl0 = __float2half_rn(h0 - __half2float(hh0));
                    fp16 hl1 = __float2half_rn(h1 - __half2float(hh1));
                    *(__half2*)(Hhi + idx) = __halves2half2(hh0, hh1);
                    *(__half2*)(Hlo + idx) = __halves2half2(hl0, hl1);
                }
            }
        }
    }
}

// ---------------- combine ----------------
__global__ void k_combine(float* __restrict__ out, const float* __restrict__ pair, int T) {
    int t = blockIdx.x;
    float w0 = g_tw[2 * t], w1 = g_tw[2 * t + 1];
    size_t p0 = (size_t)g_slot[2 * t] * DIM;
    size_t p1 = (size_t)g_slot[2 * t + 1] * DIM;
    size_t ob = (size_t)t * DIM;
    for (int d = threadIdx.x * 4; d < DIM; d += blockDim.x * 4) {
        float4 a = *(const float4*)(pair + p0 + d);
        float4 b = *(const float4*)(pair + p1 + d);
        float4 o = *(const float4*)(out + ob + d);
        o.x += w0 * a.x + w1 * b.x;
        o.y += w0 * a.y + w1 * b.y;
        o.z += w0 * a.z + w1 * b.z;
        o.w += w0 * a.w + w1 * b.w;
        *(float4*)(out + ob + d) = o;
    }
}

// ---------------- launch ----------------
extern "C" void kernel_launch(void* const* d_in, const int* in_sizes, int n_in,
                              void* d_out, int out_size) {
    const float* x  = (const float*)d_in[0];
    const float* gw = (const float*)d_in[1];
    const float* sg = (const float*)d_in[2];
    const float* su = (const float*)d_in[3];
    const float* sd = (const float*)d_in[4];
    const float* eg = (const float*)d_in[5];
    const float* eu = (const float*)d_in[6];
    const float* ed = (const float*)d_in[7];
    float* out = (float*)d_out;

    int T = in_sizes[0] / DIM;       // 8192
    int A2 = 2 * T;

    float *pG, *pPair;
    int *pOff;
    fp16 *pXhi, *pXlo, *pXGhi, *pXGlo, *pHhi, *pHlo;
    fp16 *pSG, *pSU, *pSD, *pEG, *pEU, *pED;
    cudaGetSymbolAddress((void**)&pG, g_G);
    cudaGetSymbolAddress((void**)&pPair, g_pair);
    cudaGetSymbolAddress((void**)&pOff, g_off);
    cudaGetSymbolAddress((void**)&pXhi, g_xhi);
    cudaGetSymbolAddress((void**)&pXlo, g_xlo);
    cudaGetSymbolAddress((void**)&pXGhi, g_xghi);
    cudaGetSymbolAddress((void**)&pXGlo, g_xglo);
    cudaGetSymbolAddress((void**)&pHhi, g_Hhi);
    cudaGetSymbolAddress((void**)&pHlo, g_Hlo);
    cudaGetSymbolAddress((void**)&pSG, g_sgT);
    cudaGetSymbolAddress((void**)&pSU, g_suT);
    cudaGetSymbolAddress((void**)&pSD, g_sdT);
    cudaGetSymbolAddress((void**)&pEG, g_egT);
    cudaGetSymbolAddress((void**)&pEU, g_euT);
    cudaGetSymbolAddress((void**)&pED, g_edT);

    cudaFuncSetAttribute(k_gemm_p<0>, cudaFuncAttributeMaxDynamicSharedMemorySize, GEMM_SMEM);
    cudaFuncSetAttribute(k_gemm_p<1>, cudaFuncAttributeMaxDynamicSharedMemorySize, GEMM_SMEM);

    k_init<<<1, 32>>>();
    k_router<<<(T + 7) / 8, 256>>>(x, gw, T);
    k_scan<<<1, 1>>>(out, T, (size_t)out_size > (size_t)T * DIM ? 1 : 0);
    k_scatter<<<(T + 255) / 256, 256>>>(T);

    // splits / transposes / gather
    k_split<<<(T * DIM / 4 + 255) / 256, 256>>>((const float4*)x, (__half2*)pXhi,
                                                (__half2*)pXlo, T * DIM / 4);
    k_gsplit<<<A2, 256>>>(x, (__half2*)pXGhi, (__half2*)pXGlo);
    k_tsplit<<<dim3(IDIM / 32, DIM / 32, 1), 256>>>(sg, pSG, DIM, IDIM);
    k_tsplit<<<dim3(IDIM / 32, DIM / 32, 1), 256>>>(su, pSU, DIM, IDIM);
    k_tsplit<<<dim3(DIM / 32, IDIM / 32, 1), 256>>>(sd, pSD, IDIM, DIM);
    k_tsplit<<<dim3(IDIM / 32, DIM / 32, NE), 256>>>(eg, pEG, DIM, IDIM);
    k_tsplit<<<dim3(IDIM / 32, DIM / 32, NE), 256>>>(eu, pEU, DIM, IDIM);
    k_tsplit<<<dim3(DIM / 32, IDIM / 32, NE), 256>>>(ed, pED, IDIM, DIM);

    // shared expert
    k_gemm_p<0><<<dim3(IDIM / 256, T / 128, 1), 256, GEMM_SMEM>>>(
        pXhi, pXlo, pSG, pG, nullptr, nullptr, nullptr,
        nullptr, T, IDIM, DIM, 0, DIM / BK);
    k_gemm_p<1><<<dim3(IDIM / 256, T / 128, 1), 256, GEMM_SMEM>>>(
        pXhi, pXlo, pSU, nullptr, pG, pHhi, pHlo,
        nullptr, T, IDIM, DIM, 0, DIM / BK);
    k_gemm_p<0><<<dim3(DIM / 256, T / 128, 1), 256, GEMM_SMEM>>>(
        pHhi, pHlo, pSD, out, nullptr, nullptr, nullptr,
        nullptr, T, DIM, IDIM, 0, IDIM / BK);

    // routed experts
    int mt = (A2 + 127) / 128;
    k_gemm_p<0><<<dim3(IDIM / 256, mt, NE), 256, GEMM_SMEM>>>(
        pXGhi, pXGlo, pEG, pG, nullptr, nullptr, nullptr,
        pOff, A2, IDIM, DIM, (long)DIM * IDIM, DIM / BK);
    k_gemm_p<1><<<dim3(IDIM / 256, mt, NE), 256, GEMM_SMEM>>>(
        pXGhi, pXGlo, pEU, nullptr, pG, pHhi, pHlo,
        pOff, A2, IDIM, DIM, (long)DIM * IDIM, DIM / BK);
    k_gemm_p<0><<<dim3(DIM / 256, mt, NE), 256, GEMM_SMEM>>>(
        pHhi, pHlo, pED, pPair, nullptr, nullptr, nullptr,
        pOff, A2, DIM, IDIM, (long)IDIM * DIM, IDIM / BK);

    k_combine<<<T, 256>>>(out, pPair, T);
}

// round 12
// speedup vs baseline: 1.8266x; 1.8266x over previous
#include <cuda_runtime.h>
#include <cuda_fp16.h>
#include <cstdint>
#include <math.h>

#define NE 8
#define DIM 1024
#define IDIM 2048
#define TKN_MAX 8192
#define ASG_MAX 16384

typedef __half fp16;

// ---------------- device scratch (no allocs allowed) ----------------
__device__ float g_G[(size_t)ASG_MAX * IDIM];
__device__ float g_pair[(size_t)ASG_MAX * DIM];
__device__ fp16  g_Hhi[(size_t)ASG_MAX * IDIM];
__device__ fp16  g_Hlo[(size_t)ASG_MAX * IDIM];
__device__ fp16  g_xhi[(size_t)TKN_MAX * DIM];
__device__ fp16  g_xlo[(size_t)TKN_MAX * DIM];
__device__ fp16  g_xghi[(size_t)ASG_MAX * DIM];
__device__ fp16  g_xglo[(size_t)ASG_MAX * DIM];
// transposed weights [N, K], single fp16
__device__ fp16  g_sgT[(size_t)IDIM * DIM];
__device__ fp16  g_suT[(size_t)IDIM * DIM];
__device__ fp16  g_sdT[(size_t)DIM * IDIM];
__device__ fp16  g_egT[(size_t)NE * IDIM * DIM];
__device__ fp16  g_euT[(size_t)NE * IDIM * DIM];
__device__ fp16  g_edT[(size_t)NE * DIM * IDIM];
__device__ int   g_assign[ASG_MAX];
__device__ int   g_te[ASG_MAX];
__device__ float g_tw[ASG_MAX];
__device__ int   g_slot[ASG_MAX];
__device__ int   g_counts[NE];
__device__ int   g_off[NE + 1];
__device__ int   g_cursor[NE];
__device__ float g_psum[NE];

// ---------------- mma / ldmatrix / cp.async helpers ----------------
__device__ __forceinline__ void mma_f16(float* d, const unsigned* a, const unsigned* b) {
    asm volatile("mma.sync.aligned.m16n8k16.row.col.f32.f16.f16.f32 "
                 "{%0,%1,%2,%3}, {%4,%5,%6,%7}, {%8,%9}, {%0,%1,%2,%3};"
                 : "+f"(d[0]), "+f"(d[1]), "+f"(d[2]), "+f"(d[3])
                 : "r"(a[0]), "r"(a[1]), "r"(a[2]), "r"(a[3]), "r"(b[0]), "r"(b[1]));
}
__device__ __forceinline__ void ldsm4(unsigned* r, unsigned addr) {
    asm volatile("ldmatrix.sync.aligned.m8n8.x4.shared.b16 {%0,%1,%2,%3}, [%4];"
                 : "=r"(r[0]), "=r"(r[1]), "=r"(r[2]), "=r"(r[3]) : "r"(addr));
}
#define CPA16(dst, src) \
    asm volatile("cp.async.cg.shared.global [%0], [%1], 16;" :: "r"(dst), "l"(src))
#define CP_COMMIT() asm volatile("cp.async.commit_group;" ::: "memory")
#define CP_WAIT1()  asm volatile("cp.async.wait_group 1;" ::: "memory")

__device__ __forceinline__ float silu_f(float x) { return x / (1.f + expf(-x)); }

// ---------------- init ----------------
__global__ void k_init() {
    int i = threadIdx.x;
    if (i < NE) { g_counts[i] = 0; g_psum[i] = 0.f; }
}

// ---------------- split: fp32 -> fp16 hi + fp16 lo ----------------
__global__ void k_split(const float4* __restrict__ in, __half2* __restrict__ hi,
                        __half2* __restrict__ lo, int n4) {
    int i = blockIdx.x * blockDim.x + threadIdx.x;
    if (i < n4) {
        float4 v = in[i];
        fp16 h0 = __float2half_rn(v.x), h1 = __float2half_rn(v.y);
        fp16 h2 = __float2half_rn(v.z), h3 = __float2half_rn(v.w);
        fp16 l0 = __float2half_rn(v.x - __half2float(h0));
        fp16 l1 = __float2half_rn(v.y - __half2float(h1));
        fp16 l2 = __float2half_rn(v.z - __half2float(h2));
        fp16 l3 = __float2half_rn(v.w - __half2float(h3));
        hi[2 * i]     = __halves2half2(h0, h1);
        hi[2 * i + 1] = __halves2half2(h2, h3);
        lo[2 * i]     = __halves2half2(l0, l1);
        lo[2 * i + 1] = __halves2half2(l2, l3);
    }
}

// ---------------- transpose + convert: W[K,N] fp32 -> Wt[N,K] fp16 ----------------
__global__ void k_tsplit(const float* __restrict__ W, fp16* __restrict__ hi, int K, int N) {
    __shared__ float t[32][33];
    size_t eo = (size_t)blockIdx.z * K * N;
    int k0 = blockIdx.y * 32, n0 = blockIdx.x * 32;
    int tx = threadIdx.x & 31, ty = threadIdx.x >> 5;
#pragma unroll
    for (int r = ty; r < 32; r += 8)
        t[r][tx] = W[eo + (size_t)(k0 + r) * N + n0 + tx];
    __syncthreads();
#pragma unroll
    for (int r = ty; r < 32; r += 8) {
        size_t o = eo + (size_t)(n0 + r) * K + k0 + tx;
        hi[o] = __float2half_rn(t[tx][r]);
    }
}

// ---------------- gather + split ----------------
__global__ void k_gsplit(const float* __restrict__ x, __half2* __restrict__ hi,
                         __half2* __restrict__ lo) {
    int a = blockIdx.x;
    int t = g_assign[a];
    const float4* src = (const float4*)(x + (size_t)t * DIM);
    int i = threadIdx.x;
    float4 v = src[i];
    fp16 h0 = __float2half_rn(v.x), h1 = __float2half_rn(v.y);
    fp16 h2 = __float2half_rn(v.z), h3 = __float2half_rn(v.w);
    fp16 l0 = __float2half_rn(v.x - __half2float(h0));
    fp16 l1 = __float2half_rn(v.y - __half2float(h1));
    fp16 l2 = __float2half_rn(v.z - __half2float(h2));
    fp16 l3 = __float2half_rn(v.w - __half2float(h3));
    size_t o = (size_t)a * (DIM / 2) + 2 * i;
    hi[o]     = __halves2half2(h0, h1);
    hi[o + 1] = __halves2half2(h2, h3);
    lo[o]     = __halves2half2(l0, l1);
    lo[o + 1] = __halves2half2(l2, l3);
}

// ---------------- router ----------------
__global__ void k_router(const float* __restrict__ x, const float* __restrict__ gw, int T) {
    __shared__ float sP[NE];
    if (threadIdx.x < NE) sP[threadIdx.x] = 0.f;
    __syncthreads();

    int warp = (blockIdx.x * blockDim.x + threadIdx.x) >> 5;
    int lane = threadIdx.x & 31;
    if (warp < T) {
        const float* xr = x + (size_t)warp * DIM;
        float acc[NE];
#pragma unroll
        for (int e = 0; e < NE; e++) acc[e] = 0.f;
        for (int i = lane; i < DIM; i += 32) {
            float xv = xr[i];
#pragma unroll
            for (int e = 0; e < NE; e++) acc[e] = fmaf(xv, gw[e * DIM + i], acc[e]);
        }
#pragma unroll
        for (int e = 0; e < NE; e++) {
#pragma unroll
            for (int o = 16; o; o >>= 1) acc[e] += __shfl_xor_sync(0xffffffffu, acc[e], o);
        }
        if (lane == 0) {
            float mx = acc[0];
#pragma unroll
            for (int e = 1; e < NE; e++) mx = fmaxf(mx, acc[e]);
            float ex[NE]; float s = 0.f;
#pragma unroll
            for (int e = 0; e < NE; e++) { ex[e] = expf(acc[e] - mx); s += ex[e]; }
            float inv = 1.f / s;
#pragma unroll
            for (int e = 0; e < NE; e++) atomicAdd(&sP[e], ex[e] * inv);
            int i0 = 0;
#pragma unroll
            for (int e = 1; e < NE; e++) if (acc[e] > acc[i0]) i0 = e;
            int i1 = (i0 == 0) ? 1 : 0;
#pragma unroll
            for (int e = 0; e < NE; e++) if (e != i0 && acc[e] > acc[i1]) i1 = e;
            float m2 = fmaxf(acc[i0], acc[i1]);
            float e0 = expf(acc[i0] - m2), e1 = expf(acc[i1] - m2);
            float wsum = e0 + e1;
            g_te[2 * warp] = i0; g_te[2 * warp + 1] = i1;
            g_tw[2 * warp] = e0 / wsum; g_tw[2 * warp + 1] = e1 / wsum;
            atomicAdd(&g_counts[i0], 1);
            atomicAdd(&g_counts[i1], 1);
        }
    }
    __syncthreads();
    if (threadIdx.x < NE) atomicAdd(&g_psum[threadIdx.x], sP[threadIdx.x]);
}

// ---------------- scan ----------------
__global__ void k_scan(float* __restrict__ out, int T, int write_aux) {
    if (threadIdx.x == 0 && blockIdx.x == 0) {
        int o = 0;
        float aux = 0.f;
        for (int e = 0; e < NE; e++) {
            g_off[e] = o; g_cursor[e] = o;
            float f = (float)g_counts[e] / (float)(T * 2);
            float P = g_psum[e] / (float)T;
            aux += f * P;
            o += g_counts[e];
        }
        g_off[NE] = o;
        if (write_aux) out[(size_t)T * DIM] = (float)NE * aux;
    }
}

// ---------------- scatter ----------------
__global__ void k_scatter(int T) {
    int t = blockIdx.x * blockDim.x + threadIdx.x;
    if (t < T) {
#pragma unroll
        for (int k = 0; k < 2; k++) {
            int e = g_te[2 * t + k];
            int pos = atomicAdd(&g_cursor[e], 1);
            g_assign[pos] = t;
            g_slot[2 * t + k] = pos;
        }
    }
}

// ---------------- fp16 A-split x2 HMMA GEMM: CTA 128x128, warp 64x32, occ=2 ----------------
// C[m,n] = sum_k (Ahi+Alo)[m,k] * Bt[n,k];  B single fp16, fp32 accumulate.
// BK=64 (row = 128B line), SW128 swizzle, 2-stage ring, 48KB/stage -> 2 CTAs/SM.
#define BK 64
#define STG 2
#define TILE_A_B 16384                  // 128 rows x 128B
#define OFF_ALO  TILE_A_B
#define OFF_B    (2 * TILE_A_B)
#define STAGE_B  (3 * TILE_A_B)         // 49152
#define GEMM_SMEM (STG * STAGE_B)       // 98304

template <int EPI>
__global__ __launch_bounds__(256, 2) void k_gemm_p(
    const fp16* __restrict__ Ahi, const fp16* __restrict__ Alo,
    const fp16* __restrict__ Bt,
    float* __restrict__ C, const float* __restrict__ Gbuf,
    fp16* __restrict__ Hhi, fp16* __restrict__ Hlo,
    const int* __restrict__ seg_off,
    int M, int N, int K, long strideB, int NST)
{
    int m_lo = 0, m_hi = M;
    const fp16* Bp = Bt;
    if (seg_off) {
        int s = blockIdx.z;
        m_lo = seg_off[s]; m_hi = seg_off[s + 1];
        Bp += (size_t)s * strideB;
    }
    int m0 = m_lo + blockIdx.y * 128;
    if (m0 >= m_hi) return;
    int n0 = blockIdx.x * 128;

    extern __shared__ __align__(1024) char sm[];
    int tid = threadIdx.x, lane = tid & 31, wid = tid >> 5;
    int wm = wid >> 2, wn = wid & 3;

    unsigned sbase;
    asm("{ .reg .u64 t; cvta.to.shared.u64 t, %1; cvt.u32.u64 %0, t; }"
        : "=r"(sbase) : "l"(sm));

    // ---- load addressing ----
    int chunk = tid & 7;
    int r0 = tid >> 3;                  // 0..31
    unsigned rowA[4], rowB[4];
#pragma unroll
    for (int j = 0; j < 4; j++) {
        int r = r0 + 32 * j;
        int gr = m0 + r; if (gr > M - 1) gr = M - 1;
        rowA[j] = (unsigned)((size_t)gr * K * 2) + (unsigned)(chunk * 16);
        rowB[j] = (unsigned)((size_t)(n0 + r) * K * 2) + (unsigned)(chunk * 16);
    }
    unsigned dst0 = (unsigned)(r0 * 128 + ((chunk * 16) ^ ((r0 & 7) << 4)));

    auto load_stage = [&](int stage, int buf) {
        unsigned d = sbase + (unsigned)buf * STAGE_B + dst0;
        unsigned ko = (unsigned)(stage * BK * 2);
#pragma unroll
        for (int j = 0; j < 4; j++) {
            unsigned dj = d + (unsigned)j * 4096;
            CPA16(dj,           (const char*)Ahi + rowA[j] + ko);
            CPA16(dj + OFF_ALO, (const char*)Alo + rowA[j] + ko);
            CPA16(dj + OFF_B,   (const char*)Bp  + rowB[j] + ko);
        }
    };

    // ---- accumulators ----
    float acc[4][4][4];
#pragma unroll
    for (int i = 0; i < 4; i++)
#pragma unroll
        for (int j = 0; j < 4; j++)
#pragma unroll
            for (int r = 0; r < 4; r++) acc[i][j][r] = 0.f;

    unsigned laneRow = (unsigned)((lane & 15) * 128);
    unsigned chunkb = (unsigned)((lane >> 4) << 4);
    unsigned swx = (unsigned)((lane & 7) << 4);

    // ---- prologue ----
    if (0 < NST) load_stage(0, 0);
    CP_COMMIT();
    if (1 < NST) load_stage(1, 1);
    CP_COMMIT();

    for (int i = 0; i < NST; i++) {
        CP_WAIT1();
        __syncthreads();

        unsigned tb = sbase + (unsigned)(i & 1) * STAGE_B;

#pragma unroll
        for (int ks = 0; ks < 4; ks++) {
            unsigned xoff = (((unsigned)(ks * 32)) | chunkb) ^ swx;
            unsigned bfr[4][2];
#pragma unroll
            for (int nb = 0; nb < 2; nb++) {
                unsigned ro = (unsigned)((wn * 32 + nb * 16) * 128) + laneRow + xoff;
                unsigned t[4];
                ldsm4(t, tb + OFF_B + ro);
                bfr[2 * nb][0] = t[0]; bfr[2 * nb][1] = t[2];
                bfr[2 * nb + 1][0] = t[1]; bfr[2 * nb + 1][1] = t[3];
            }
#pragma unroll
            for (int mi = 0; mi < 4; mi++) {
                unsigned ro = (unsigned)((wm * 64 + mi * 16) * 128) + laneRow + xoff;
                unsigned ah[4], al[4];
                ldsm4(ah, tb + ro);
                ldsm4(al, tb + OFF_ALO + ro);
#pragma unroll
                for (int ni = 0; ni < 4; ni++) mma_f16(acc[mi][ni], ah, bfr[ni]);
#pragma unroll
                for (int ni = 0; ni < 4; ni++) mma_f16(acc[mi][ni], al, bfr[ni]);
            }
        }
        __syncthreads();
        if (i + 2 < NST) load_stage(i + 2, i & 1);
        CP_COMMIT();
    }

    // ---- epilogue ----
    int mrow = m0 + wm * 64 + (lane >> 2);
    int mcol = n0 + wn * 32 + ((lane & 3) << 1);
#pragma unroll
    for (int mi = 0; mi < 4; mi++) {
#pragma unroll
        for (int half = 0; half < 2; half++) {
            int r = mrow + mi * 16 + half * 8;
            if (r >= m_hi) continue;
#pragma unroll
            for (int ni = 0; ni < 4; ni++) {
                int c = mcol + ni * 8;
                size_t idx = (size_t)r * N + c;
                float v0 = acc[mi][ni][2 * half];
                float v1 = acc[mi][ni][2 * half + 1];
                if (EPI == 0) {
                    *(float2*)(C + idx) = make_float2(v0, v1);
                } else {
                    float2 g = *(const float2*)(Gbuf + idx);
                    float h0 = silu_f(g.x) * v0;
                    float h1 = silu_f(g.y) * v1;
                    fp16 hh0 = __float2half_rn(h0);
                    fp16 hh1 = __float2half_rn(h1);
                    fp16 hl0 = __float2half_rn(h0 - __half2float(hh0));
                    fp16 hl1 = __float2half_rn(h1 - __half2float(hh1));
                    *(__half2*)(Hhi + idx) = __halves2half2(hh0, hh1);
                    *(__half2*)(Hlo + idx) = __halves2half2(hl0, hl1);
                }
            }
        }
    }
}

// ---------------- combine ----------------
__global__ void k_combine(float* __restrict__ out, const float* __restrict__ pair, int T) {
    int t = blockIdx.x;
    float w0 = g_tw[2 * t], w1 = g_tw[2 * t + 1];
    size_t p0 = (size_t)g_slot[2 * t] * DIM;
    size_t p1 = (size_t)g_slot[2 * t + 1] * DIM;
    size_t ob = (size_t)t * DIM;
    for (int d = threadIdx.x * 4; d < DIM; d += blockDim.x * 4) {
        float4 a = *(const float4*)(pair + p0 + d);
        float4 b = *(const float4*)(pair + p1 + d);
        float4 o = *(const float4*)(out + ob + d);
        o.x += w0 * a.x + w1 * b.x;
        o.y += w0 * a.y + w1 * b.y;
        o.z += w0 * a.z + w1 * b.z;
        o.w += w0 * a.w + w1 * b.w;
        *(float4*)(out + ob + d) = o;
    }
}

// ---------------- launch ----------------
extern "C" void kernel_launch(void* const* d_in, const int* in_sizes, int n_in,
                              void* d_out, int out_size) {
    const float* x  = (const float*)d_in[0];
    const float* gw = (const float*)d_in[1];
    const float* sg = (const float*)d_in[2];
    const float* su = (const float*)d_in[3];
    const float* sd = (const float*)d_in[4];
    const float* eg = (const float*)d_in[5];
    const float* eu = (const float*)d_in[6];
    const float* ed = (const float*)d_in[7];
    float* out = (float*)d_out;

    int T = in_sizes[0] / DIM;       // 8192
    int A2 = 2 * T;

    float *pG, *pPair;
    int *pOff;
    fp16 *pXhi, *pXlo, *pXGhi, *pXGlo, *pHhi, *pHlo;
    fp16 *pSG, *pSU, *pSD, *pEG, *pEU, *pED;
    cudaGetSymbolAddress((void**)&pG, g_G);
    cudaGetSymbolAddress((void**)&pPair, g_pair);
    cudaGetSymbolAddress((void**)&pOff, g_off);
    cudaGetSymbolAddress((void**)&pXhi, g_xhi);
    cudaGetSymbolAddress((void**)&pXlo, g_xlo);
    cudaGetSymbolAddress((void**)&pXGhi, g_xghi);
    cudaGetSymbolAddress((void**)&pXGlo, g_xglo);
    cudaGetSymbolAddress((void**)&pHhi, g_Hhi);
    cudaGetSymbolAddress((void**)&pHlo, g_Hlo);
    cudaGetSymbolAddress((void**)&pSG, g_sgT);
    cudaGetSymbolAddress((void**)&pSU, g_suT);
    cudaGetSymbolAddress((void**)&pSD, g_sdT);
    cudaGetSymbolAddress((void**)&pEG, g_egT);
    cudaGetSymbolAddress((void**)&pEU, g_euT);
    cudaGetSymbolAddress((void**)&pED, g_edT);

    cudaFuncSetAttribute(k_gemm_p<0>, cudaFuncAttributeMaxDynamicSharedMemorySize, GEMM_SMEM);
    cudaFuncSetAttribute(k_gemm_p<1>, cudaFuncAttributeMaxDynamicSharedMemorySize, GEMM_SMEM);

    k_init<<<1, 32>>>();
    k_router<<<(T + 7) / 8, 256>>>(x, gw, T);
    k_scan<<<1, 1>>>(out, T, (size_t)out_size > (size_t)T * DIM ? 1 : 0);
    k_scatter<<<(T + 255) / 256, 256>>>(T);

    // splits / transposes / gather
    k_split<<<(T * DIM / 4 + 255) / 256, 256>>>((const float4*)x, (__half2*)pXhi,
                                                (__half2*)pXlo, T * DIM / 4);
    k_gsplit<<<A2, 256>>>(x, (__half2*)pXGhi, (__half2*)pXGlo);
    k_tsplit<<<dim3(IDIM / 32, DIM / 32, 1), 256>>>(sg, pSG, DIM, IDIM);
    k_tsplit<<<dim3(IDIM / 32, DIM / 32, 1), 256>>>(su, pSU, DIM, IDIM);
    k_tsplit<<<dim3(DIM / 32, IDIM / 32, 1), 256>>>(sd, pSD, IDIM, DIM);
    k_tsplit<<<dim3(IDIM / 32, DIM / 32, NE), 256>>>(eg, pEG, DIM, IDIM);
    k_tsplit<<<dim3(IDIM / 32, DIM / 32, NE), 256>>>(eu, pEU, DIM, IDIM);
    k_tsplit<<<dim3(DIM / 32, IDIM / 32, NE), 256>>>(ed, pED, IDIM, DIM);

    // shared expert
    k_gemm_p<0><<<dim3(IDIM / 128, T / 128, 1), 256, GEMM_SMEM>>>(
        pXhi, pXlo, pSG, pG, nullptr, nullptr, nullptr,
        nullptr, T, IDIM, DIM, 0, DIM / BK);
    k_gemm_p<1><<<dim3(IDIM / 128, T / 128, 1), 256, GEMM_SMEM>>>(
        pXhi, pXlo, pSU, nullptr, pG, pHhi, pHlo,
        nullptr, T, IDIM, DIM, 0, DIM / BK);
    k_gemm_p<0><<<dim3(DIM / 128, T / 128, 1), 256, GEMM_SMEM>>>(
        pHhi, pHlo, pSD, out, nullptr, nullptr, nullptr,
        nullptr, T, DIM, IDIM, 0, IDIM / BK);

    // routed experts
    int mt = (A2 + 127) / 128;
    k_gemm_p<0><<<dim3(IDIM / 128, mt, NE), 256, GEMM_SMEM>>>(
        pXGhi, pXGlo, pEG, pG, nullptr, nullptr, nullptr,
        pOff, A2, IDIM, DIM, (long)DIM * IDIM, DIM / BK);
    k_gemm_p<1><<<dim3(IDIM / 128, mt, NE), 256, GEMM_SMEM>>>(
        pXGhi, pXGlo, pEU, nullptr, pG, pHhi, pHlo,
        pOff, A2, IDIM, DIM, (long)DIM * IDIM, DIM / BK);
    k_gemm_p<0><<<dim3(DIM / 128, mt, NE), 256, GEMM_SMEM>>>(
        pHhi, pHlo, pED, pPair, nullptr, nullptr, nullptr,
        pOff, A2, DIM, IDIM, (long)IDIM * DIM, IDIM / BK);

    k_combine<<<T, 256>>>(out, pPair, T);
}

// round 15
// speedup vs baseline: 2.7163x; 1.4871x over previous
#include <cuda_runtime.h>
#include <cuda_fp16.h>
#include <cstdint>
#include <math.h>

#define NE 8
#define DIM 1024
#define IDIM 2048
#define TKN_MAX 8192
#define ASG_MAX 16384

typedef __half fp16;

// ---------------- device scratch (no allocs allowed) ----------------
__device__ float g_G[(size_t)ASG_MAX * IDIM];
__device__ float g_pair[(size_t)ASG_MAX * DIM];
__device__ fp16  g_H[(size_t)ASG_MAX * IDIM];
__device__ fp16  g_x16[(size_t)TKN_MAX * DIM];
__device__ fp16  g_xg16[(size_t)ASG_MAX * DIM];
// transposed weights [N, K], fp16
__device__ fp16  g_sgT[(size_t)IDIM * DIM];
__device__ fp16  g_suT[(size_t)IDIM * DIM];
__device__ fp16  g_sdT[(size_t)DIM * IDIM];
__device__ fp16  g_egT[(size_t)NE * IDIM * DIM];
__device__ fp16  g_euT[(size_t)NE * IDIM * DIM];
__device__ fp16  g_edT[(size_t)NE * DIM * IDIM];
__device__ int   g_assign[ASG_MAX];
__device__ int   g_te[ASG_MAX];
__device__ float g_tw[ASG_MAX];
__device__ int   g_slot[ASG_MAX];
__device__ int   g_counts[NE];
__device__ int   g_off[NE + 1];
__device__ int   g_cursor[NE];
__device__ float g_psum[NE];

// ---------------- mma / ldmatrix / cp.async helpers ----------------
__device__ __forceinline__ void mma_f16(float* d, const unsigned* a, const unsigned* b) {
    asm volatile("mma.sync.aligned.m16n8k16.row.col.f32.f16.f16.f32 "
                 "{%0,%1,%2,%3}, {%4,%5,%6,%7}, {%8,%9}, {%0,%1,%2,%3};"
                 : "+f"(d[0]), "+f"(d[1]), "+f"(d[2]), "+f"(d[3])
                 : "r"(a[0]), "r"(a[1]), "r"(a[2]), "r"(a[3]), "r"(b[0]), "r"(b[1]));
}
__device__ __forceinline__ void ldsm4(unsigned* r, unsigned addr) {
    asm volatile("ldmatrix.sync.aligned.m8n8.x4.shared.b16 {%0,%1,%2,%3}, [%4];"
                 : "=r"(r[0]), "=r"(r[1]), "=r"(r[2]), "=r"(r[3]) : "r"(addr));
}
#define CPA16(dst, src) \
    asm volatile("cp.async.cg.shared.global [%0], [%1], 16;" :: "r"(dst), "l"(src))
#define CP_COMMIT() asm volatile("cp.async.commit_group;" ::: "memory")
#define CP_WAIT1()  asm volatile("cp.async.wait_group 1;" ::: "memory")

__device__ __forceinline__ float silu_f(float x) { return x / (1.f + expf(-x)); }

// ---------------- init ----------------
__global__ void k_init() {
    int i = threadIdx.x;
    if (i < NE) { g_counts[i] = 0; g_psum[i] = 0.f; }
}

// ---------------- convert: fp32 -> fp16 ----------------
__global__ void k_cvt(const float4* __restrict__ in, __half2* __restrict__ o16, int n4) {
    int i = blockIdx.x * blockDim.x + threadIdx.x;
    if (i < n4) {
        float4 v = in[i];
        o16[2 * i]     = __halves2half2(__float2half_rn(v.x), __float2half_rn(v.y));
        o16[2 * i + 1] = __halves2half2(__float2half_rn(v.z), __float2half_rn(v.w));
    }
}

// ---------------- transpose + convert: W[K,N] fp32 -> Wt[N,K] fp16 ----------------
__global__ void k_tsplit(const float* __restrict__ W, fp16* __restrict__ hi, int K, int N) {
    __shared__ float t[32][33];
    size_t eo = (size_t)blockIdx.z * K * N;
    int k0 = blockIdx.y * 32, n0 = blockIdx.x * 32;
    int tx = threadIdx.x & 31, ty = threadIdx.x >> 5;
#pragma unroll
    for (int r = ty; r < 32; r += 8)
        t[r][tx] = W[eo + (size_t)(k0 + r) * N + n0 + tx];
    __syncthreads();
#pragma unroll
    for (int r = ty; r < 32; r += 8) {
        size_t o = eo + (size_t)(n0 + r) * K + k0 + tx;
        hi[o] = __float2half_rn(t[tx][r]);
    }
}

// ---------------- gather + convert ----------------
__global__ void k_gcvt(const float* __restrict__ x, __half2* __restrict__ o16) {
    int a = blockIdx.x;
    int t = g_assign[a];
    const float4* src = (const float4*)(x + (size_t)t * DIM);
    int i = threadIdx.x;
    float4 v = src[i];
    size_t o = (size_t)a * (DIM / 2) + 2 * i;
    o16[o]     = __halves2half2(__float2half_rn(v.x), __float2half_rn(v.y));
    o16[o + 1] = __halves2half2(__float2half_rn(v.z), __float2half_rn(v.w));
}

// ---------------- router ----------------
__global__ void k_router(const float* __restrict__ x, const float* __restrict__ gw, int T) {
    __shared__ float sP[NE];
    if (threadIdx.x < NE) sP[threadIdx.x] = 0.f;
    __syncthreads();

    int warp = (blockIdx.x * blockDim.x + threadIdx.x) >> 5;
    int lane = threadIdx.x & 31;
    if (warp < T) {
        const float* xr = x + (size_t)warp * DIM;
        float acc[NE];
#pragma unroll
        for (int e = 0; e < NE; e++) acc[e] = 0.f;
        for (int i = lane; i < DIM; i += 32) {
            float xv = xr[i];
#pragma unroll
            for (int e = 0; e < NE; e++) acc[e] = fmaf(xv, gw[e * DIM + i], acc[e]);
        }
#pragma unroll
        for (int e = 0; e < NE; e++) {
#pragma unroll
            for (int o = 16; o; o >>= 1) acc[e] += __shfl_xor_sync(0xffffffffu, acc[e], o);
        }
        if (lane == 0) {
            float mx = acc[0];
#pragma unroll
            for (int e = 1; e < NE; e++) mx = fmaxf(mx, acc[e]);
            float ex[NE]; float s = 0.f;
#pragma unroll
            for (int e = 0; e < NE; e++) { ex[e] = expf(acc[e] - mx); s += ex[e]; }
            float inv = 1.f / s;
#pragma unroll
            for (int e = 0; e < NE; e++) atomicAdd(&sP[e], ex[e] * inv);
            int i0 = 0;
#pragma unroll
            for (int e = 1; e < NE; e++) if (acc[e] > acc[i0]) i0 = e;
            int i1 = (i0 == 0) ? 1 : 0;
#pragma unroll
            for (int e = 0; e < NE; e++) if (e != i0 && acc[e] > acc[i1]) i1 = e;
            float m2 = fmaxf(acc[i0], acc[i1]);
            float e0 = expf(acc[i0] - m2), e1 = expf(acc[i1] - m2);
            float wsum = e0 + e1;
            g_te[2 * warp] = i0; g_te[2 * warp + 1] = i1;
            g_tw[2 * warp] = e0 / wsum; g_tw[2 * warp + 1] = e1 / wsum;
            atomicAdd(&g_counts[i0], 1);
            atomicAdd(&g_counts[i1], 1);
        }
    }
    __syncthreads();
    if (threadIdx.x < NE) atomicAdd(&g_psum[threadIdx.x], sP[threadIdx.x]);
}

// ---------------- scan ----------------
__global__ void k_scan(float* __restrict__ out, int T, int write_aux) {
    if (threadIdx.x == 0 && blockIdx.x == 0) {
        int o = 0;
        float aux = 0.f;
        for (int e = 0; e < NE; e++) {
            g_off[e] = o; g_cursor[e] = o;
            float f = (float)g_counts[e] / (float)(T * 2);
            float P = g_psum[e] / (float)T;
            aux += f * P;
            o += g_counts[e];
        }
        g_off[NE] = o;
        if (write_aux) out[(size_t)T * DIM] = (float)NE * aux;
    }
}

// ---------------- scatter ----------------
__global__ void k_scatter(int T) {
    int t = blockIdx.x * blockDim.x + threadIdx.x;
    if (t < T) {
#pragma unroll
        for (int k = 0; k < 2; k++) {
            int e = g_te[2 * t + k];
            int pos = atomicAdd(&g_cursor[e], 1);
            g_assign[pos] = t;
            g_slot[2 * t + k] = pos;
        }
    }
}

// ---------------- fp16 HMMA GEMM: CTA 128x128, warp 64x32, occ=2, 3-stage ----------------
// C[m,n] = sum_k A16[m,k] * Bt[n,k]; fp32 accumulate.
// BK=64 (row = 128B line), SW128 swizzle, 3-stage ring, 32KB/stage -> 2 CTAs/SM.
#define BK 64
#define STG 3
#define TILE_A_B 16384                  // 128 rows x 128B
#define OFF_B    TILE_A_B
#define STAGE_B  (2 * TILE_A_B)         // 32768
#define GEMM_SMEM (STG * STAGE_B)       // 98304

template <int EPI>
__global__ __launch_bounds__(256, 2) void k_gemm_p(
    const fp16* __restrict__ A16,
    const fp16* __restrict__ Bt,
    float* __restrict__ C, const float* __restrict__ Gbuf,
    fp16* __restrict__ H16,
    const int* __restrict__ seg_off,
    int M, int N, int K, long strideB, int NST)
{
    int m_lo = 0, m_hi = M;
    const fp16* Bp = Bt;
    if (seg_off) {
        int s = blockIdx.z;
        m_lo = seg_off[s]; m_hi = seg_off[s + 1];
        Bp += (size_t)s * strideB;
    }
    int m0 = m_lo + blockIdx.y * 128;
    if (m0 >= m_hi) return;
    int n0 = blockIdx.x * 128;

    extern __shared__ __align__(1024) char sm[];
    int tid = threadIdx.x, lane = tid & 31, wid = tid >> 5;
    int wm = wid >> 2, wn = wid & 3;

    unsigned sbase;
    asm("{ .reg .u64 t; cvta.to.shared.u64 t, %1; cvt.u32.u64 %0, t; }"
        : "=r"(sbase) : "l"(sm));

    // ---- load addressing ----
    int chunk = tid & 7;
    int r0 = tid >> 3;                  // 0..31
    unsigned rowA[4], rowB[4];
#pragma unroll
    for (int j = 0; j < 4; j++) {
        int r = r0 + 32 * j;
        int gr = m0 + r; if (gr > M - 1) gr = M - 1;
        rowA[j] = (unsigned)((size_t)gr * K * 2) + (unsigned)(chunk * 16);
        rowB[j] = (unsigned)((size_t)(n0 + r) * K * 2) + (unsigned)(chunk * 16);
    }
    unsigned dst0 = (unsigned)(r0 * 128 + ((chunk * 16) ^ ((r0 & 7) << 4)));

    auto load_stage = [&](int stage, int buf) {
        unsigned d = sbase + (unsigned)buf * STAGE_B + dst0;
        unsigned ko = (unsigned)(stage * BK * 2);
#pragma unroll
        for (int j = 0; j < 4; j++) {
            unsigned dj = d + (unsigned)j * 4096;
            CPA16(dj,         (const char*)A16 + rowA[j] + ko);
            CPA16(dj + OFF_B, (const char*)Bp  + rowB[j] + ko);
        }
    };

    // ---- accumulators ----
    float acc[4][4][4];
#pragma unroll
    for (int i = 0; i < 4; i++)
#pragma unroll
        for (int j = 0; j < 4; j++)
#pragma unroll
            for (int r = 0; r < 4; r++) acc[i][j][r] = 0.f;

    unsigned laneRow = (unsigned)((lane & 15) * 128);
    unsigned chunkb = (unsigned)((lane >> 4) << 4);
    unsigned swx = (unsigned)((lane & 7) << 4);

    // ---- prologue ----
    if (0 < NST) load_stage(0, 0);
    CP_COMMIT();
    if (1 < NST) load_stage(1, 1);
    CP_COMMIT();

    for (int i = 0; i < NST; i++) {
        CP_WAIT1();
        __syncthreads();

        unsigned tb = sbase + (unsigned)(i % STG) * STAGE_B;

#pragma unroll
        for (int ks = 0; ks < 4; ks++) {
            unsigned xoff = (((unsigned)(ks * 32)) | chunkb) ^ swx;
            unsigned bfr[4][2];
#pragma unroll
            for (int nb = 0; nb < 2; nb++) {
                unsigned ro = (unsigned)((wn * 32 + nb * 16) * 128) + laneRow + xoff;
                unsigned t[4];
                ldsm4(t, tb + OFF_B + ro);
                bfr[2 * nb][0] = t[0]; bfr[2 * nb][1] = t[2];
                bfr[2 * nb + 1][0] = t[1]; bfr[2 * nb + 1][1] = t[3];
            }
#pragma unroll
            for (int mi = 0; mi < 4; mi++) {
                unsigned ro = (unsigned)((wm * 64 + mi * 16) * 128) + laneRow + xoff;
                unsigned ah[4];
                ldsm4(ah, tb + ro);
#pragma unroll
                for (int ni = 0; ni < 4; ni++) mma_f16(acc[mi][ni], ah, bfr[ni]);
            }
        }
        __syncthreads();
        if (i + 2 < NST) load_stage(i + 2, (i + 2) % STG);
        CP_COMMIT();
    }

    // ---- epilogue ----
    int mrow = m0 + wm * 64 + (lane >> 2);
    int mcol = n0 + wn * 32 + ((lane & 3) << 1);
#pragma unroll
    for (int mi = 0; mi < 4; mi++) {
#pragma unroll
        for (int half = 0; half < 2; half++) {
            int r = mrow + mi * 16 + half * 8;
            if (r >= m_hi) continue;
#pragma unroll
            for (int ni = 0; ni < 4; ni++) {
                int c = mcol + ni * 8;
                size_t idx = (size_t)r * N + c;
                float v0 = acc[mi][ni][2 * half];
                float v1 = acc[mi][ni][2 * half + 1];
                if (EPI == 0) {
                    *(float2*)(C + idx) = make_float2(v0, v1);
                } else {
                    float2 g = *(const float2*)(Gbuf + idx);
                    float h0 = silu_f(g.x) * v0;
                    float h1 = silu_f(g.y) * v1;
                    *(__half2*)(H16 + idx) =
                        __halves2half2(__float2half_rn(h0), __float2half_rn(h1));
                }
            }
        }
    }
}

// ---------------- combine ----------------
__global__ void k_combine(float* __restrict__ out, const float* __restrict__ pair, int T) {
    int t = blockIdx.x;
    float w0 = g_tw[2 * t], w1 = g_tw[2 * t + 1];
    size_t p0 = (size_t)g_slot[2 * t] * DIM;
    size_t p1 = (size_t)g_slot[2 * t + 1] * DIM;
    size_t ob = (size_t)t * DIM;
    for (int d = threadIdx.x * 4; d < DIM; d += blockDim.x * 4) {
        float4 a = *(const float4*)(pair + p0 + d);
        float4 b = *(const float4*)(pair + p1 + d);
        float4 o = *(const float4*)(out + ob + d);
        o.x += w0 * a.x + w1 * b.x;
        o.y += w0 * a.y + w1 * b.y;
        o.z += w0 * a.z + w1 * b.z;
        o.w += w0 * a.w + w1 * b.w;
        *(float4*)(out + ob + d) = o;
    }
}

// ---------------- launch ----------------
extern "C" void kernel_launch(void* const* d_in, const int* in_sizes, int n_in,
                              void* d_out, int out_size) {
    const float* x  = (const float*)d_in[0];
    const float* gw = (const float*)d_in[1];
    const float* sg = (const float*)d_in[2];
    const float* su = (const float*)d_in[3];
    const float* sd = (const float*)d_in[4];
    const float* eg = (const float*)d_in[5];
    const float* eu = (const float*)d_in[6];
    const float* ed = (const float*)d_in[7];
    float* out = (float*)d_out;

    int T = in_sizes[0] / DIM;       // 8192
    int A2 = 2 * T;

    float *pG, *pPair;
    int *pOff;
    fp16 *pX16, *pXG16, *pH;
    fp16 *pSG, *pSU, *pSD, *pEG, *pEU, *pED;
    cudaGetSymbolAddress((void**)&pG, g_G);
    cudaGetSymbolAddress((void**)&pPair, g_pair);
    cudaGetSymbolAddress((void**)&pOff, g_off);
    cudaGetSymbolAddress((void**)&pX16, g_x16);
    cudaGetSymbolAddress((void**)&pXG16, g_xg16);
    cudaGetSymbolAddress((void**)&pH, g_H);
    cudaGetSymbolAddress((void**)&pSG, g_sgT);
    cudaGetSymbolAddress((void**)&pSU, g_suT);
    cudaGetSymbolAddress((void**)&pSD, g_sdT);
    cudaGetSymbolAddress((void**)&pEG, g_egT);
    cudaGetSymbolAddress((void**)&pEU, g_euT);
    cudaGetSymbolAddress((void**)&pED, g_edT);

    cudaFuncSetAttribute(k_gemm_p<0>, cudaFuncAttributeMaxDynamicSharedMemorySize, GEMM_SMEM);
    cudaFuncSetAttribute(k_gemm_p<1>, cudaFuncAttributeMaxDynamicSharedMemorySize, GEMM_SMEM);

    k_init<<<1, 32>>>();
    k_router<<<(T + 7) / 8, 256>>>(x, gw, T);
    k_scan<<<1, 1>>>(out, T, (size_t)out_size > (size_t)T * DIM ? 1 : 0);
    k_scatter<<<(T + 255) / 256, 256>>>(T);

    // converts / transposes / gather
    k_cvt<<<(T * DIM / 4 + 255) / 256, 256>>>((const float4*)x, (__half2*)pX16, T * DIM / 4);
    k_gcvt<<<A2, 256>>>(x, (__half2*)pXG16);
    k_tsplit<<<dim3(IDIM / 32, DIM / 32, 1), 256>>>(sg, pSG, DIM, IDIM);
    k_tsplit<<<dim3(IDIM / 32, DIM / 32, 1), 256>>>(su, pSU, DIM, IDIM);
    k_tsplit<<<dim3(DIM / 32, IDIM / 32, 1), 256>>>(sd, pSD, IDIM, DIM);
    k_tsplit<<<dim3(IDIM / 32, DIM / 32, NE), 256>>>(eg, pEG, DIM, IDIM);
    k_tsplit<<<dim3(IDIM / 32, DIM / 32, NE), 256>>>(eu, pEU, DIM, IDIM);
    k_tsplit<<<dim3(DIM / 32, IDIM / 32, NE), 256>>>(ed, pED, IDIM, DIM);

    // shared expert
    k_gemm_p<0><<<dim3(IDIM / 128, T / 128, 1), 256, GEMM_SMEM>>>(
        pX16, pSG, pG, nullptr, nullptr,
        nullptr, T, IDIM, DIM, 0, DIM / BK);
    k_gemm_p<1><<<dim3(IDIM / 128, T / 128, 1), 256, GEMM_SMEM>>>(
        pX16, pSU, nullptr, pG, pH,
        nullptr, T, IDIM, DIM, 0, DIM / BK);
    k_gemm_p<0><<<dim3(DIM / 128, T / 128, 1), 256, GEMM_SMEM>>>(
        pH, pSD, out, nullptr, nullptr,
        nullptr, T, DIM, IDIM, 0, IDIM / BK);

    // routed experts
    int mt = (A2 + 127) / 128;
    k_gemm_p<0><<<dim3(IDIM / 128, mt, NE), 256, GEMM_SMEM>>>(
        pXG16, pEG, pG, nullptr, nullptr,
        pOff, A2, IDIM, DIM, (long)DIM * IDIM, DIM / BK);
    k_gemm_p<1><<<dim3(IDIM / 128, mt, NE), 256, GEMM_SMEM>>>(
        pXG16, pEU, nullptr, pG, pH,
        pOff, A2, IDIM, DIM, (long)DIM * IDIM, DIM / BK);
    k_gemm_p<0><<<dim3(DIM / 128, mt, NE), 256, GEMM_SMEM>>>(
        pH, pED, pPair, nullptr, nullptr,
        pOff, A2, DIM, IDIM, (long)IDIM * DIM, IDIM / BK);

    k_combine<<<T, 256>>>(out, pPair, T);
}

// round 16
// speedup vs baseline: 2.9659x; 1.0919x over previous
#include <cuda_runtime.h>
#include <cuda_fp16.h>
#include <cstdint>
#include <math.h>

#define NE 8
#define DIM 1024
#define IDIM 2048
#define TKN_MAX 8192
#define ASG_MAX 16384

typedef __half fp16;

// ---------------- device scratch (no allocs allowed) ----------------
__device__ float g_pair[(size_t)ASG_MAX * DIM];
__device__ fp16  g_H[(size_t)ASG_MAX * IDIM];
__device__ fp16  g_x16[(size_t)TKN_MAX * DIM];
__device__ fp16  g_xg16[(size_t)ASG_MAX * DIM];
// transposed weights [N, K], fp16; gate/up interleaved by column pairs
__device__ fp16  g_sguT[(size_t)2 * IDIM * DIM];
__device__ fp16  g_sdT[(size_t)DIM * IDIM];
__device__ fp16  g_eguT[(size_t)NE * 2 * IDIM * DIM];
__device__ fp16  g_edT[(size_t)NE * DIM * IDIM];
__device__ int   g_assign[ASG_MAX];
__device__ int   g_te[ASG_MAX];
__device__ float g_tw[ASG_MAX];
__device__ int   g_slot[ASG_MAX];
__device__ int   g_counts[NE];
__device__ int   g_off[NE + 1];
__device__ int   g_cursor[NE];
__device__ float g_psum[NE];

// ---------------- mma / ldmatrix / cp.async helpers ----------------
__device__ __forceinline__ void mma_f16(float* d, const unsigned* a, const unsigned* b) {
    asm volatile("mma.sync.aligned.m16n8k16.row.col.f32.f16.f16.f32 "
                 "{%0,%1,%2,%3}, {%4,%5,%6,%7}, {%8,%9}, {%0,%1,%2,%3};"
                 : "+f"(d[0]), "+f"(d[1]), "+f"(d[2]), "+f"(d[3])
                 : "r"(a[0]), "r"(a[1]), "r"(a[2]), "r"(a[3]), "r"(b[0]), "r"(b[1]));
}
__device__ __forceinline__ void ldsm4(unsigned* r, unsigned addr) {
    asm volatile("ldmatrix.sync.aligned.m8n8.x4.shared.b16 {%0,%1,%2,%3}, [%4];"
                 : "=r"(r[0]), "=r"(r[1]), "=r"(r[2]), "=r"(r[3]) : "r"(addr));
}
#define CPA16(dst, src) \
    asm volatile("cp.async.cg.shared.global [%0], [%1], 16;" :: "r"(dst), "l"(src))
#define CP_COMMIT() asm volatile("cp.async.commit_group;" ::: "memory")
#define CP_WAIT1()  asm volatile("cp.async.wait_group 1;" ::: "memory")

__device__ __forceinline__ float silu_f(float x) { return x / (1.f + expf(-x)); }

// ---------------- init ----------------
__global__ void k_init() {
    int i = threadIdx.x;
    if (i < NE) { g_counts[i] = 0; g_psum[i] = 0.f; }
}

// ---------------- convert: fp32 -> fp16 ----------------
__global__ void k_cvt(const float4* __restrict__ in, __half2* __restrict__ o16, int n4) {
    int i = blockIdx.x * blockDim.x + threadIdx.x;
    if (i < n4) {
        float4 v = in[i];
        o16[2 * i]     = __halves2half2(__float2half_rn(v.x), __float2half_rn(v.y));
        o16[2 * i + 1] = __halves2half2(__float2half_rn(v.z), __float2half_rn(v.w));
    }
}

// ---------------- transpose + convert: W[K,N] fp32 -> Wt[N,K] fp16 ----------------
__global__ void k_tsplit(const float* __restrict__ W, fp16* __restrict__ o, int K, int N) {
    __shared__ float t[32][33];
    size_t eo = (size_t)blockIdx.z * K * N;
    int k0 = blockIdx.y * 32, n0 = blockIdx.x * 32;
    int tx = threadIdx.x & 31, ty = threadIdx.x >> 5;
#pragma unroll
    for (int r = ty; r < 32; r += 8)
        t[r][tx] = W[eo + (size_t)(k0 + r) * N + n0 + tx];
    __syncthreads();
#pragma unroll
    for (int r = ty; r < 32; r += 8) {
        size_t o_i = eo + (size_t)(n0 + r) * K + k0 + tx;
        o[o_i] = __float2half_rn(t[tx][r]);
    }
}

// ---------------- fused transpose: gate/up -> interleaved [2N, K] fp16 ----------------
// out row 2j = Wg[:,j], row 2j+1 = Wu[:,j]
__global__ void k_tspf(const float* __restrict__ Wg, const float* __restrict__ Wu,
                       fp16* __restrict__ o, int K, int N) {
    __shared__ float tg[32][33], tu[32][33];
    size_t eo_in = (size_t)blockIdx.z * K * N;
    size_t eo_out = (size_t)blockIdx.z * 2 * K * N;
    int k0 = blockIdx.y * 32, n0 = blockIdx.x * 32;
    int tx = threadIdx.x & 31, ty = threadIdx.x >> 5;
#pragma unroll
    for (int r = ty; r < 32; r += 8) {
        size_t src = eo_in + (size_t)(k0 + r) * N + n0 + tx;
        tg[r][tx] = Wg[src];
        tu[r][tx] = Wu[src];
    }
    __syncthreads();
#pragma unroll
    for (int r = ty; r < 32; r += 8) {
        size_t ro = eo_out + (size_t)(2 * (n0 + r)) * K + k0 + tx;
        o[ro]     = __float2half_rn(tg[tx][r]);
        o[ro + K] = __float2half_rn(tu[tx][r]);
    }
}

// ---------------- gather + convert ----------------
__global__ void k_gcvt(const float* __restrict__ x, __half2* __restrict__ o16) {
    int a = blockIdx.x;
    int t = g_assign[a];
    const float4* src = (const float4*)(x + (size_t)t * DIM);
    int i = threadIdx.x;
    float4 v = src[i];
    size_t o = (size_t)a * (DIM / 2) + 2 * i;
    o16[o]     = __halves2half2(__float2half_rn(v.x), __float2half_rn(v.y));
    o16[o + 1] = __halves2half2(__float2half_rn(v.z), __float2half_rn(v.w));
}

// ---------------- router ----------------
__global__ void k_router(const float* __restrict__ x, const float* __restrict__ gw, int T) {
    __shared__ float sP[NE];
    if (threadIdx.x < NE) sP[threadIdx.x] = 0.f;
    __syncthreads();

    int warp = (blockIdx.x * blockDim.x + threadIdx.x) >> 5;
    int lane = threadIdx.x & 31;
    if (warp < T) {
        const float* xr = x + (size_t)warp * DIM;
        float acc[NE];
#pragma unroll
        for (int e = 0; e < NE; e++) acc[e] = 0.f;
        for (int i = lane; i < DIM; i += 32) {
            float xv = xr[i];
#pragma unroll
            for (int e = 0; e < NE; e++) acc[e] = fmaf(xv, gw[e * DIM + i], acc[e]);
        }
#pragma unroll
        for (int e = 0; e < NE; e++) {
#pragma unroll
            for (int o = 16; o; o >>= 1) acc[e] += __shfl_xor_sync(0xffffffffu, acc[e], o);
        }
        if (lane == 0) {
            float mx = acc[0];
#pragma unroll
            for (int e = 1; e < NE; e++) mx = fmaxf(mx, acc[e]);
            float ex[NE]; float s = 0.f;
#pragma unroll
            for (int e = 0; e < NE; e++) { ex[e] = expf(acc[e] - mx); s += ex[e]; }
            float inv = 1.f / s;
#pragma unroll
            for (int e = 0; e < NE; e++) atomicAdd(&sP[e], ex[e] * inv);
            int i0 = 0;
#pragma unroll
            for (int e = 1; e < NE; e++) if (acc[e] > acc[i0]) i0 = e;
            int i1 = (i0 == 0) ? 1 : 0;
#pragma unroll
            for (int e = 0; e < NE; e++) if (e != i0 && acc[e] > acc[i1]) i1 = e;
            float m2 = fmaxf(acc[i0], acc[i1]);
            float e0 = expf(acc[i0] - m2), e1 = expf(acc[i1] - m2);
            float wsum = e0 + e1;
            g_te[2 * warp] = i0; g_te[2 * warp + 1] = i1;
            g_tw[2 * warp] = e0 / wsum; g_tw[2 * warp + 1] = e1 / wsum;
            atomicAdd(&g_counts[i0], 1);
            atomicAdd(&g_counts[i1], 1);
        }
    }
    __syncthreads();
    if (threadIdx.x < NE) atomicAdd(&g_psum[threadIdx.x], sP[threadIdx.x]);
}

// ---------------- scan ----------------
__global__ void k_scan(float* __restrict__ out, int T, int write_aux) {
    if (threadIdx.x == 0 && blockIdx.x == 0) {
        int o = 0;
        float aux = 0.f;
        for (int e = 0; e < NE; e++) {
            g_off[e] = o; g_cursor[e] = o;
            float f = (float)g_counts[e] / (float)(T * 2);
            float P = g_psum[e] / (float)T;
            aux += f * P;
            o += g_counts[e];
        }
        g_off[NE] = o;
        if (write_aux) out[(size_t)T * DIM] = (float)NE * aux;
    }
}

// ---------------- scatter ----------------
__global__ void k_scatter(int T) {
    int t = blockIdx.x * blockDim.x + threadIdx.x;
    if (t < T) {
#pragma unroll
        for (int k = 0; k < 2; k++) {
            int e = g_te[2 * t + k];
            int pos = atomicAdd(&g_cursor[e], 1);
            g_assign[pos] = t;
            g_slot[2 * t + k] = pos;
        }
    }
}

// ---------------- fp16 HMMA GEMM: CTA 128x128, warp 64x32, occ=2, 3-stage ----------------
// EPI==0: C[m,n] = sum_k A16[m,k]*Bt[n,k], fp32 out.
// EPI==2: fused swiglu — B has gate/up interleaved (col 2j=gate_j, 2j+1=up_j);
//         epilogue writes H16[m, j] = silu(gate)*up.  (H stride = N/2)
#define BK 64
#define STG 3
#define TILE_A_B 16384                  // 128 rows x 128B
#define OFF_B    TILE_A_B
#define STAGE_B  (2 * TILE_A_B)         // 32768
#define GEMM_SMEM (STG * STAGE_B)       // 98304

template <int EPI>
__global__ __launch_bounds__(256, 2) void k_gemm_p(
    const fp16* __restrict__ A16,
    const fp16* __restrict__ Bt,
    float* __restrict__ C,
    fp16* __restrict__ H16,
    const int* __restrict__ seg_off,
    int M, int N, int K, long strideB, int NST)
{
    int m_lo = 0, m_hi = M;
    const fp16* Bp = Bt;
    if (seg_off) {
        int s = blockIdx.z;
        m_lo = seg_off[s]; m_hi = seg_off[s + 1];
        Bp += (size_t)s * strideB;
    }
    int m0 = m_lo + blockIdx.y * 128;
    if (m0 >= m_hi) return;
    int n0 = blockIdx.x * 128;

    extern __shared__ __align__(1024) char sm[];
    int tid = threadIdx.x, lane = tid & 31, wid = tid >> 5;
    int wm = wid >> 2, wn = wid & 3;

    unsigned sbase;
    asm("{ .reg .u64 t; cvta.to.shared.u64 t, %1; cvt.u32.u64 %0, t; }"
        : "=r"(sbase) : "l"(sm));

    // ---- load addressing ----
    int chunk = tid & 7;
    int r0 = tid >> 3;                  // 0..31
    unsigned rowA[4], rowB[4];
#pragma unroll
    for (int j = 0; j < 4; j++) {
        int r = r0 + 32 * j;
        int gr = m0 + r; if (gr > M - 1) gr = M - 1;
        rowA[j] = (unsigned)((size_t)gr * K * 2) + (unsigned)(chunk * 16);
        rowB[j] = (unsigned)((size_t)(n0 + r) * K * 2) + (unsigned)(chunk * 16);
    }
    unsigned dst0 = (unsigned)(r0 * 128 + ((chunk * 16) ^ ((r0 & 7) << 4)));

    auto load_stage = [&](int stage, int buf) {
        unsigned d = sbase + (unsigned)buf * STAGE_B + dst0;
        unsigned ko = (unsigned)(stage * BK * 2);
#pragma unroll
        for (int j = 0; j < 4; j++) {
            unsigned dj = d + (unsigned)j * 4096;
            CPA16(dj,         (const char*)A16 + rowA[j] + ko);
            CPA16(dj + OFF_B, (const char*)Bp  + rowB[j] + ko);
        }
    };

    // ---- accumulators ----
    float acc[4][4][4];
#pragma unroll
    for (int i = 0; i < 4; i++)
#pragma unroll
        for (int j = 0; j < 4; j++)
#pragma unroll
            for (int r = 0; r < 4; r++) acc[i][j][r] = 0.f;

    unsigned laneRow = (unsigned)((lane & 15) * 128);
    unsigned chunkb = (unsigned)((lane >> 4) << 4);
    unsigned swx = (unsigned)((lane & 7) << 4);

    // ---- prologue ----
    if (0 < NST) load_stage(0, 0);
    CP_COMMIT();
    if (1 < NST) load_stage(1, 1);
    CP_COMMIT();

    for (int i = 0; i < NST; i++) {
        CP_WAIT1();
        __syncthreads();

        unsigned tb = sbase + (unsigned)(i % STG) * STAGE_B;

#pragma unroll
        for (int ks = 0; ks < 4; ks++) {
            unsigned xoff = (((unsigned)(ks * 32)) | chunkb) ^ swx;
            unsigned bfr[4][2];
#pragma unroll
            for (int nb = 0; nb < 2; nb++) {
                unsigned ro = (unsigned)((wn * 32 + nb * 16) * 128) + laneRow + xoff;
                unsigned t[4];
                ldsm4(t, tb + OFF_B + ro);
                bfr[2 * nb][0] = t[0]; bfr[2 * nb][1] = t[2];
                bfr[2 * nb + 1][0] = t[1]; bfr[2 * nb + 1][1] = t[3];
            }
#pragma unroll
            for (int mi = 0; mi < 4; mi++) {
                unsigned ro = (unsigned)((wm * 64 + mi * 16) * 128) + laneRow + xoff;
                unsigned ah[4];
                ldsm4(ah, tb + ro);
#pragma unroll
                for (int ni = 0; ni < 4; ni++) mma_f16(acc[mi][ni], ah, bfr[ni]);
            }
        }
        __syncthreads();
        if (i + 2 < NST) load_stage(i + 2, (i + 2) % STG);
        CP_COMMIT();
    }

    // ---- epilogue ----
    int mrow = m0 + wm * 64 + (lane >> 2);
    int mcol = n0 + wn * 32 + ((lane & 3) << 1);
#pragma unroll
    for (int mi = 0; mi < 4; mi++) {
#pragma unroll
        for (int half = 0; half < 2; half++) {
            int r = mrow + mi * 16 + half * 8;
            if (r >= m_hi) continue;
#pragma unroll
            for (int ni = 0; ni < 4; ni++) {
                int c = mcol + ni * 8;
                float v0 = acc[mi][ni][2 * half];
                float v1 = acc[mi][ni][2 * half + 1];
                if (EPI == 0) {
                    *(float2*)(C + (size_t)r * N + c) = make_float2(v0, v1);
                } else {
                    // c even; col c = gate j, col c+1 = up j, j = c/2
                    float h = silu_f(v0) * v1;
                    H16[(size_t)r * (N >> 1) + (c >> 1)] = __float2half_rn(h);
                }
            }
        }
    }
}

// ---------------- combine ----------------
__global__ void k_combine(float* __restrict__ out, const float* __restrict__ pair, int T) {
    int t = blockIdx.x;
    float w0 = g_tw[2 * t], w1 = g_tw[2 * t + 1];
    size_t p0 = (size_t)g_slot[2 * t] * DIM;
    size_t p1 = (size_t)g_slot[2 * t + 1] * DIM;
    size_t ob = (size_t)t * DIM;
    for (int d = threadIdx.x * 4; d < DIM; d += blockDim.x * 4) {
        float4 a = *(const float4*)(pair + p0 + d);
        float4 b = *(const float4*)(pair + p1 + d);
        float4 o = *(const float4*)(out + ob + d);
        o.x += w0 * a.x + w1 * b.x;
        o.y += w0 * a.y + w1 * b.y;
        o.z += w0 * a.z + w1 * b.z;
        o.w += w0 * a.w + w1 * b.w;
        *(float4*)(out + ob + d) = o;
    }
}

// ---------------- launch ----------------
extern "C" void kernel_launch(void* const* d_in, const int* in_sizes, int n_in,
                              void* d_out, int out_size) {
    const float* x  = (const float*)d_in[0];
    const float* gw = (const float*)d_in[1];
    const float* sg = (const float*)d_in[2];
    const float* su = (const float*)d_in[3];
    const float* sd = (const float*)d_in[4];
    const float* eg = (const float*)d_in[5];
    const float* eu = (const float*)d_in[6];
    const float* ed = (const float*)d_in[7];
    float* out = (float*)d_out;

    int T = in_sizes[0] / DIM;       // 8192
    int A2 = 2 * T;

    float *pPair;
    int *pOff;
    fp16 *pX16, *pXG16, *pH;
    fp16 *pSGU, *pSD, *pEGU, *pED;
    cudaGetSymbolAddress((void**)&pPair, g_pair);
    cudaGetSymbolAddress((void**)&pOff, g_off);
    cudaGetSymbolAddress((void**)&pX16, g_x16);
    cudaGetSymbolAddress((void**)&pXG16, g_xg16);
    cudaGetSymbolAddress((void**)&pH, g_H);
    cudaGetSymbolAddress((void**)&pSGU, g_sguT);
    cudaGetSymbolAddress((void**)&pSD, g_sdT);
    cudaGetSymbolAddress((void**)&pEGU, g_eguT);
    cudaGetSymbolAddress((void**)&pED, g_edT);

    cudaFuncSetAttribute(k_gemm_p<0>, cudaFuncAttributeMaxDynamicSharedMemorySize, GEMM_SMEM);
    cudaFuncSetAttribute(k_gemm_p<2>, cudaFuncAttributeMaxDynamicSharedMemorySize, GEMM_SMEM);

    k_init<<<1, 32>>>();
    k_router<<<(T + 7) / 8, 256>>>(x, gw, T);
    k_scan<<<1, 1>>>(out, T, (size_t)out_size > (size_t)T * DIM ? 1 : 0);
    k_scatter<<<(T + 255) / 256, 256>>>(T);

    // converts / transposes / gather
    k_cvt<<<(T * DIM / 4 + 255) / 256, 256>>>((const float4*)x, (__half2*)pX16, T * DIM / 4);
    k_gcvt<<<A2, 256>>>(x, (__half2*)pXG16);
    k_tspf<<<dim3(IDIM / 32, DIM / 32, 1), 256>>>(sg, su, pSGU, DIM, IDIM);
    k_tsplit<<<dim3(DIM / 32, IDIM / 32, 1), 256>>>(sd, pSD, IDIM, DIM);
    k_tspf<<<dim3(IDIM / 32, DIM / 32, NE), 256>>>(eg, eu, pEGU, DIM, IDIM);
    k_tsplit<<<dim3(DIM / 32, IDIM / 32, NE), 256>>>(ed, pED, IDIM, DIM);

    // shared expert: fused gate+up -> H, then down -> out
    k_gemm_p<2><<<dim3(2 * IDIM / 128, T / 128, 1), 256, GEMM_SMEM>>>(
        pX16, pSGU, nullptr, pH,
        nullptr, T, 2 * IDIM, DIM, 0, DIM / BK);
    k_gemm_p<0><<<dim3(DIM / 128, T / 128, 1), 256, GEMM_SMEM>>>(
        pH, pSD, out, nullptr,
        nullptr, T, DIM, IDIM, 0, IDIM / BK);

    // routed experts
    int mt = (A2 + 127) / 128;
    k_gemm_p<2><<<dim3(2 * IDIM / 128, mt, NE), 256, GEMM_SMEM>>>(
        pXG16, pEGU, nullptr, pH,
        pOff, A2, 2 * IDIM, DIM, (long)2 * IDIM * DIM, DIM / BK);
    k_gemm_p<0><<<dim3(DIM / 128, mt, NE), 256, GEMM_SMEM>>>(
        pH, pED, pPair, nullptr,
        pOff, A2, DIM, IDIM, (long)IDIM * DIM, IDIM / BK);

    k_combine<<<T, 256>>>(out, pPair, T);
}

// round 17
// speedup vs baseline: 3.0975x; 1.0444x over previous
#include <cuda_runtime.h>
#include <cuda_fp16.h>
#include <cstdint>
#include <math.h>

#define NE 8
#define DIM 1024
#define IDIM 2048
#define TKN_MAX 8192
#define ASG_MAX 16384

typedef __half fp16;

// ---------------- device scratch (no allocs allowed) ----------------
__device__ float g_pair[(size_t)ASG_MAX * DIM];
__device__ fp16  g_H[(size_t)ASG_MAX * IDIM];
__device__ fp16  g_x16[(size_t)TKN_MAX * DIM];
__device__ fp16  g_xg16[(size_t)ASG_MAX * DIM];
// transposed weights [N, K], fp16; gate/up interleaved by column pairs
__device__ fp16  g_sguT[(size_t)2 * IDIM * DIM];
__device__ fp16  g_sdT[(size_t)DIM * IDIM];
__device__ fp16  g_eguT[(size_t)NE * 2 * IDIM * DIM];
__device__ fp16  g_edT[(size_t)NE * DIM * IDIM];
__device__ int   g_assign[ASG_MAX];
__device__ int   g_te[ASG_MAX];
__device__ float g_tw[ASG_MAX];
__device__ int   g_slot[ASG_MAX];
__device__ int   g_counts[NE];
__device__ int   g_off[NE + 1];
__device__ int   g_cursor[NE];
__device__ float g_psum[NE];

// ---------------- mma / ldmatrix / cp.async helpers ----------------
__device__ __forceinline__ void mma_f16(float* d, const unsigned* a, const unsigned* b) {
    asm volatile("mma.sync.aligned.m16n8k16.row.col.f32.f16.f16.f32 "
                 "{%0,%1,%2,%3}, {%4,%5,%6,%7}, {%8,%9}, {%0,%1,%2,%3};"
                 : "+f"(d[0]), "+f"(d[1]), "+f"(d[2]), "+f"(d[3])
                 : "r"(a[0]), "r"(a[1]), "r"(a[2]), "r"(a[3]), "r"(b[0]), "r"(b[1]));
}
__device__ __forceinline__ void ldsm4(unsigned* r, unsigned addr) {
    asm volatile("ldmatrix.sync.aligned.m8n8.x4.shared.b16 {%0,%1,%2,%3}, [%4];"
                 : "=r"(r[0]), "=r"(r[1]), "=r"(r[2]), "=r"(r[3]) : "r"(addr));
}
#define CPA16(dst, src) \
    asm volatile("cp.async.cg.shared.global [%0], [%1], 16;" :: "r"(dst), "l"(src))
#define CP_COMMIT() asm volatile("cp.async.commit_group;" ::: "memory")
#define CP_WAIT1()  asm volatile("cp.async.wait_group 1;" ::: "memory")

__device__ __forceinline__ float silu_f(float x) { return x / (1.f + expf(-x)); }

// ---------------- init ----------------
__global__ void k_init() {
    int i = threadIdx.x;
    if (i < NE) { g_counts[i] = 0; g_psum[i] = 0.f; }
}

// ---------------- convert: fp32 -> fp16 ----------------
__global__ void k_cvt(const float4* __restrict__ in, __half2* __restrict__ o16, int n4) {
    int i = blockIdx.x * blockDim.x + threadIdx.x;
    if (i < n4) {
        float4 v = in[i];
        o16[2 * i]     = __halves2half2(__float2half_rn(v.x), __float2half_rn(v.y));
        o16[2 * i + 1] = __halves2half2(__float2half_rn(v.z), __float2half_rn(v.w));
    }
}

// ---------------- transpose + convert: W[K,N] fp32 -> Wt[N,K] fp16 ----------------
__global__ void k_tsplit(const float* __restrict__ W, fp16* __restrict__ o, int K, int N) {
    __shared__ float t[32][33];
    size_t eo = (size_t)blockIdx.z * K * N;
    int k0 = blockIdx.y * 32, n0 = blockIdx.x * 32;
    int tx = threadIdx.x & 31, ty = threadIdx.x >> 5;
#pragma unroll
    for (int r = ty; r < 32; r += 8)
        t[r][tx] = W[eo + (size_t)(k0 + r) * N + n0 + tx];
    __syncthreads();
#pragma unroll
    for (int r = ty; r < 32; r += 8) {
        size_t o_i = eo + (size_t)(n0 + r) * K + k0 + tx;
        o[o_i] = __float2half_rn(t[tx][r]);
    }
}

// ---------------- fused transpose: gate/up -> interleaved [2N, K] fp16 ----------------
__global__ void k_tspf(const float* __restrict__ Wg, const float* __restrict__ Wu,
                       fp16* __restrict__ o, int K, int N) {
    __shared__ float tg[32][33], tu[32][33];
    size_t eo_in = (size_t)blockIdx.z * K * N;
    size_t eo_out = (size_t)blockIdx.z * 2 * K * N;
    int k0 = blockIdx.y * 32, n0 = blockIdx.x * 32;
    int tx = threadIdx.x & 31, ty = threadIdx.x >> 5;
#pragma unroll
    for (int r = ty; r < 32; r += 8) {
        size_t src = eo_in + (size_t)(k0 + r) * N + n0 + tx;
        tg[r][tx] = Wg[src];
        tu[r][tx] = Wu[src];
    }
    __syncthreads();
#pragma unroll
    for (int r = ty; r < 32; r += 8) {
        size_t ro = eo_out + (size_t)(2 * (n0 + r)) * K + k0 + tx;
        o[ro]     = __float2half_rn(tg[tx][r]);
        o[ro + K] = __float2half_rn(tu[tx][r]);
    }
}

// ---------------- gather + convert ----------------
__global__ void k_gcvt(const float* __restrict__ x, __half2* __restrict__ o16) {
    int a = blockIdx.x;
    int t = g_assign[a];
    const float4* src = (const float4*)(x + (size_t)t * DIM);
    int i = threadIdx.x;
    float4 v = src[i];
    size_t o = (size_t)a * (DIM / 2) + 2 * i;
    o16[o]     = __halves2half2(__float2half_rn(v.x), __float2half_rn(v.y));
    o16[o + 1] = __halves2half2(__float2half_rn(v.z), __float2half_rn(v.w));
}

// ---------------- router ----------------
__global__ void k_router(const float* __restrict__ x, const float* __restrict__ gw, int T) {
    __shared__ float sP[NE];
    if (threadIdx.x < NE) sP[threadIdx.x] = 0.f;
    __syncthreads();

    int warp = (blockIdx.x * blockDim.x + threadIdx.x) >> 5;
    int lane = threadIdx.x & 31;
    if (warp < T) {
        const float* xr = x + (size_t)warp * DIM;
        float acc[NE];
#pragma unroll
        for (int e = 0; e < NE; e++) acc[e] = 0.f;
        for (int i = lane; i < DIM; i += 32) {
            float xv = xr[i];
#pragma unroll
            for (int e = 0; e < NE; e++) acc[e] = fmaf(xv, gw[e * DIM + i], acc[e]);
        }
#pragma unroll
        for (int e = 0; e < NE; e++) {
#pragma unroll
            for (int o = 16; o; o >>= 1) acc[e] += __shfl_xor_sync(0xffffffffu, acc[e], o);
        }
        if (lane == 0) {
            float mx = acc[0];
#pragma unroll
            for (int e = 1; e < NE; e++) mx = fmaxf(mx, acc[e]);
            float ex[NE]; float s = 0.f;
#pragma unroll
            for (int e = 0; e < NE; e++) { ex[e] = expf(acc[e] - mx); s += ex[e]; }
            float inv = 1.f / s;
#pragma unroll
            for (int e = 0; e < NE; e++) atomicAdd(&sP[e], ex[e] * inv);
            int i0 = 0;
#pragma unroll
            for (int e = 1; e < NE; e++) if (acc[e] > acc[i0]) i0 = e;
            int i1 = (i0 == 0) ? 1 : 0;
#pragma unroll
            for (int e = 0; e < NE; e++) if (e != i0 && acc[e] > acc[i1]) i1 = e;
            float m2 = fmaxf(acc[i0], acc[i1]);
            float e0 = expf(acc[i0] - m2), e1 = expf(acc[i1] - m2);
            float wsum = e0 + e1;
            g_te[2 * warp] = i0; g_te[2 * warp + 1] = i1;
            g_tw[2 * warp] = e0 / wsum; g_tw[2 * warp + 1] = e1 / wsum;
            atomicAdd(&g_counts[i0], 1);
            atomicAdd(&g_counts[i1], 1);
        }
    }
    __syncthreads();
    if (threadIdx.x < NE) atomicAdd(&g_psum[threadIdx.x], sP[threadIdx.x]);
}

// ---------------- scan ----------------
__global__ void k_scan(float* __restrict__ out, int T, int write_aux) {
    if (threadIdx.x == 0 && blockIdx.x == 0) {
        int o = 0;
        float aux = 0.f;
        for (int e = 0; e < NE; e++) {
            g_off[e] = o; g_cursor[e] = o;
            float f = (float)g_counts[e] / (float)(T * 2);
            float P = g_psum[e] / (float)T;
            aux += f * P;
            o += g_counts[e];
        }
        g_off[NE] = o;
        if (write_aux) out[(size_t)T * DIM] = (float)NE * aux;
    }
}

// ---------------- scatter ----------------
__global__ void k_scatter(int T) {
    int t = blockIdx.x * blockDim.x + threadIdx.x;
    if (t < T) {
#pragma unroll
        for (int k = 0; k < 2; k++) {
            int e = g_te[2 * t + k];
            int pos = atomicAdd(&g_cursor[e], 1);
            g_assign[pos] = t;
            g_slot[2 * t + k] = pos;
        }
    }
}

// ---------------- fp16 HMMA GEMM: CTA 128x128, 4 warps, warp 64x64, occ=2 ----------------
// EPI==0: C[m,n] = sum_k A16[m,k]*Bt[n,k], fp32 out.
// EPI==2: fused swiglu (gate/up interleaved cols) -> H16[m, c/2] = silu(gate)*up.
#define BK 64
#define STG 3
#define TILE_A_B 16384                  // 128 rows x 128B
#define OFF_B    TILE_A_B
#define STAGE_B  (2 * TILE_A_B)         // 32768
#define GEMM_SMEM (STG * STAGE_B)       // 98304
#define GTHREADS 128

template <int EPI>
__global__ __launch_bounds__(GTHREADS, 2) void k_gemm_p(
    const fp16* __restrict__ A16,
    const fp16* __restrict__ Bt,
    float* __restrict__ C,
    fp16* __restrict__ H16,
    const int* __restrict__ seg_off,
    int M, int N, int K, long strideB, int NST)
{
    int m_lo = 0, m_hi = M;
    const fp16* Bp = Bt;
    if (seg_off) {
        int s = blockIdx.z;
        m_lo = seg_off[s]; m_hi = seg_off[s + 1];
        Bp += (size_t)s * strideB;
    }
    int m0 = m_lo + blockIdx.y * 128;
    if (m0 >= m_hi) return;
    int n0 = blockIdx.x * 128;

    extern __shared__ __align__(1024) char sm[];
    int tid = threadIdx.x, lane = tid & 31, wid = tid >> 5;
    int wm = wid >> 1, wn = wid & 1;     // 2x2 warps, warp tile 64x64

    unsigned sbase;
    asm("{ .reg .u64 t; cvta.to.shared.u64 t, %1; cvt.u32.u64 %0, t; }"
        : "=r"(sbase) : "l"(sm));

    // ---- load addressing: 128 threads, chunk tid&7 of rows (tid>>3)+16j ----
    int chunk = tid & 7;
    int r0 = tid >> 3;                  // 0..15
    unsigned rowA[8], rowB[8];
#pragma unroll
    for (int j = 0; j < 8; j++) {
        int r = r0 + 16 * j;
        int gr = m0 + r; if (gr > M - 1) gr = M - 1;
        rowA[j] = (unsigned)((size_t)gr * K * 2) + (unsigned)(chunk * 16);
        rowB[j] = (unsigned)((size_t)(n0 + r) * K * 2) + (unsigned)(chunk * 16);
    }
    unsigned dst0 = (unsigned)(r0 * 128 + ((chunk * 16) ^ ((r0 & 7) << 4)));

    auto load_stage = [&](int stage, int buf) {
        unsigned d = sbase + (unsigned)buf * STAGE_B + dst0;
        unsigned ko = (unsigned)(stage * BK * 2);
#pragma unroll
        for (int j = 0; j < 8; j++) {
            unsigned dj = d + (unsigned)j * 2048;
            CPA16(dj,         (const char*)A16 + rowA[j] + ko);
            CPA16(dj + OFF_B, (const char*)Bp  + rowB[j] + ko);
        }
    };

    // ---- accumulators: 4 mi x 8 ni ----
    float acc[4][8][4];
#pragma unroll
    for (int i = 0; i < 4; i++)
#pragma unroll
        for (int j = 0; j < 8; j++)
#pragma unroll
            for (int r = 0; r < 4; r++) acc[i][j][r] = 0.f;

    unsigned laneRow = (unsigned)((lane & 15) * 128);
    unsigned chunkb = (unsigned)((lane >> 4) << 4);
    unsigned swx = (unsigned)((lane & 7) << 4);

    // ---- prologue ----
    if (0 < NST) load_stage(0, 0);
    CP_COMMIT();
    if (1 < NST) load_stage(1, 1);
    CP_COMMIT();

    for (int i = 0; i < NST; i++) {
        CP_WAIT1();
        __syncthreads();

        unsigned tb = sbase + (unsigned)(i % STG) * STAGE_B;

#pragma unroll
        for (int ks = 0; ks < 4; ks++) {
            unsigned xoff = (((unsigned)(ks * 32)) | chunkb) ^ swx;
            unsigned bfr[8][2];
#pragma unroll
            for (int nb = 0; nb < 4; nb++) {
                unsigned ro = (unsigned)((wn * 64 + nb * 16) * 128) + laneRow + xoff;
                unsigned t[4];
                ldsm4(t, tb + OFF_B + ro);
                bfr[2 * nb][0] = t[0]; bfr[2 * nb][1] = t[2];
                bfr[2 * nb + 1][0] = t[1]; bfr[2 * nb + 1][1] = t[3];
            }
#pragma unroll
            for (int mi = 0; mi < 4; mi++) {
                unsigned ro = (unsigned)((wm * 64 + mi * 16) * 128) + laneRow + xoff;
                unsigned ah[4];
                ldsm4(ah, tb + ro);
#pragma unroll
                for (int ni = 0; ni < 8; ni++) mma_f16(acc[mi][ni], ah, bfr[ni]);
            }
        }
        __syncthreads();
        if (i + 2 < NST) load_stage(i + 2, (i + 2) % STG);
        CP_COMMIT();
    }

    // ---- epilogue ----
    int mrow = m0 + wm * 64 + (lane >> 2);
    int mcol = n0 + wn * 64 + ((lane & 3) << 1);
#pragma unroll
    for (int mi = 0; mi < 4; mi++) {
#pragma unroll
        for (int half = 0; half < 2; half++) {
            int r = mrow + mi * 16 + half * 8;
            if (r >= m_hi) continue;
#pragma unroll
            for (int ni = 0; ni < 8; ni++) {
                int c = mcol + ni * 8;
                float v0 = acc[mi][ni][2 * half];
                float v1 = acc[mi][ni][2 * half + 1];
                if (EPI == 0) {
                    *(float2*)(C + (size_t)r * N + c) = make_float2(v0, v1);
                } else {
                    float h = silu_f(v0) * v1;
                    H16[(size_t)r * (N >> 1) + (c >> 1)] = __float2half_rn(h);
                }
            }
        }
    }
}

// ---------------- combine ----------------
__global__ void k_combine(float* __restrict__ out, const float* __restrict__ pair, int T) {
    int t = blockIdx.x;
    float w0 = g_tw[2 * t], w1 = g_tw[2 * t + 1];
    size_t p0 = (size_t)g_slot[2 * t] * DIM;
    size_t p1 = (size_t)g_slot[2 * t + 1] * DIM;
    size_t ob = (size_t)t * DIM;
    for (int d = threadIdx.x * 4; d < DIM; d += blockDim.x * 4) {
        float4 a = *(const float4*)(pair + p0 + d);
        float4 b = *(const float4*)(pair + p1 + d);
        float4 o = *(const float4*)(out + ob + d);
        o.x += w0 * a.x + w1 * b.x;
        o.y += w0 * a.y + w1 * b.y;
        o.z += w0 * a.z + w1 * b.z;
        o.w += w0 * a.w + w1 * b.w;
        *(float4*)(out + ob + d) = o;
    }
}

// ---------------- launch ----------------
extern "C" void kernel_launch(void* const* d_in, const int* in_sizes, int n_in,
                              void* d_out, int out_size) {
    const float* x  = (const float*)d_in[0];
    const float* gw = (const float*)d_in[1];
    const float* sg = (const float*)d_in[2];
    const float* su = (const float*)d_in[3];
    const float* sd = (const float*)d_in[4];
    const float* eg = (const float*)d_in[5];
    const float* eu = (const float*)d_in[6];
    const float* ed = (const float*)d_in[7];
    float* out = (float*)d_out;

    int T = in_sizes[0] / DIM;       // 8192
    int A2 = 2 * T;

    float *pPair;
    int *pOff;
    fp16 *pX16, *pXG16, *pH;
    fp16 *pSGU, *pSD, *pEGU, *pED;
    cudaGetSymbolAddress((void**)&pPair, g_pair);
    cudaGetSymbolAddress((void**)&pOff, g_off);
    cudaGetSymbolAddress((void**)&pX16, g_x16);
    cudaGetSymbolAddress((void**)&pXG16, g_xg16);
    cudaGetSymbolAddress((void**)&pH, g_H);
    cudaGetSymbolAddress((void**)&pSGU, g_sguT);
    cudaGetSymbolAddress((void**)&pSD, g_sdT);
    cudaGetSymbolAddress((void**)&pEGU, g_eguT);
    cudaGetSymbolAddress((void**)&pED, g_edT);

    cudaFuncSetAttribute(k_gemm_p<0>, cudaFuncAttributeMaxDynamicSharedMemorySize, GEMM_SMEM);
    cudaFuncSetAttribute(k_gemm_p<2>, cudaFuncAttributeMaxDynamicSharedMemorySize, GEMM_SMEM);

    k_init<<<1, 32>>>();
    k_router<<<(T + 7) / 8, 256>>>(x, gw, T);
    k_scan<<<1, 1>>>(out, T, (size_t)out_size > (size_t)T * DIM ? 1 : 0);
    k_scatter<<<(T + 255) / 256, 256>>>(T);

    // converts / transposes / gather
    k_cvt<<<(T * DIM / 4 + 255) / 256, 256>>>((const float4*)x, (__half2*)pX16, T * DIM / 4);
    k_gcvt<<<A2, 256>>>(x, (__half2*)pXG16);
    k_tspf<<<dim3(IDIM / 32, DIM / 32, 1), 256>>>(sg, su, pSGU, DIM, IDIM);
    k_tsplit<<<dim3(DIM / 32, IDIM / 32, 1), 256>>>(sd, pSD, IDIM, DIM);
    k_tspf<<<dim3(IDIM / 32, DIM / 32, NE), 256>>>(eg, eu, pEGU, DIM, IDIM);
    k_tsplit<<<dim3(DIM / 32, IDIM / 32, NE), 256>>>(ed, pED, IDIM, DIM);

    // shared expert: fused gate+up -> H, then down -> out
    k_gemm_p<2><<<dim3(2 * IDIM / 128, T / 128, 1), GTHREADS, GEMM_SMEM>>>(
        pX16, pSGU, nullptr, pH,
        nullptr, T, 2 * IDIM, DIM, 0, DIM / BK);
    k_gemm_p<0><<<dim3(DIM / 128, T / 128, 1), GTHREADS, GEMM_SMEM>>>(
        pH, pSD, out, nullptr,
        nullptr, T, DIM, IDIM, 0, IDIM / BK);

    // routed experts
    int mt = (A2 + 127) / 128;
    k_gemm_p<2><<<dim3(2 * IDIM / 128, mt, NE), GTHREADS, GEMM_SMEM>>>(
        pXG16, pEGU, nullptr, pH,
        pOff, A2, 2 * IDIM, DIM, (long)2 * IDIM * DIM, DIM / BK);
    k_gemm_p<0><<<dim3(DIM / 128, mt, NE), GTHREADS, GEMM_SMEM>>>(
        pH, pED, pPair, nullptr,
        pOff, A2, DIM, IDIM, (long)IDIM * DIM, IDIM / BK);

    k_combine<<<T, 256>>>(out, pPair, T);
}